// round 2
// baseline (speedup 1.0000x reference)
#include <cuda_runtime.h>
#include <math.h>

#define T_    512
#define B_    64
#define IN_   256
#define H_    1024
#define H3_   3072
#define OUT_  50257

// ---------------- device scratch (no allocations allowed) ----------------
__device__ float g_gi[(size_t)T_ * B_ * H3_];   // [T][B][3H] precomputed input gates (+b_ih)
__device__ float g_h0[B_ * H_];
__device__ float g_h1[B_ * H_];

typedef unsigned long long u64;

// packed f32x2 FMA: acc(lo,hi) += a(lo,hi) * b(lo,hi)
#define FMA2(acc, a, b) asm("fma.rn.f32x2 %0, %1, %2, %0;" : "+l"(acc) : "l"(a), "l"(b))

static __device__ __forceinline__ float lo32(u64 v){ return __uint_as_float((unsigned)(v & 0xffffffffull)); }
static __device__ __forceinline__ float hi32(u64 v){ return __uint_as_float((unsigned)(v >> 32)); }

static __device__ __forceinline__ float sigmoidf_(float x){ return 1.0f / (1.0f + expf(-x)); }
static __device__ __forceinline__ float tanhf_(float x){
    float e = expf(-2.0f * fabsf(x));
    float t = (1.0f - e) / (1.0f + e);
    return copysignf(t, x);
}

// ---------------- init h0 = 0 ----------------
__global__ void zero_h_kernel(){
    int i = blockIdx.x * blockDim.x + threadIdx.x;
    if (i < B_ * H_) g_h0[i] = 0.0f;
}

// ---------------- GI = in_seq @ W_ih^T + b_ih ----------------
// grid (48, 512): x = 64-col block of 3072, y = t. block 256 threads, 64x64 tile, KT=16.
__global__ __launch_bounds__(256) void gi_kernel(const float* __restrict__ x,
                                                 const float* __restrict__ Wih,
                                                 const float* __restrict__ bih)
{
    __shared__ __align__(16) float  As[16][72];    // [k][m] transposed
    __shared__ __align__(16) float2 Bsd[16][66];   // [k][j] duplicated (w,w)

    const int tid = threadIdx.x;
    const int tx = tid & 15, ty = tid >> 4;
    const int lrow = tid >> 2, lkq = tid & 3;

    const int t  = blockIdx.y;
    const int j0 = blockIdx.x * 64;

    const float* arow = x   + (size_t)lrow * (T_ * IN_) + (size_t)t * IN_;
    const float* brow = Wih + (size_t)(j0 + lrow) * IN_;

    u64 acc[4][2];
    #pragma unroll
    for (int j = 0; j < 4; j++){ acc[j][0] = 0ull; acc[j][1] = 0ull; }

    for (int k0 = 0; k0 < IN_; k0 += 16){
        float4 av = *(const float4*)(arow + k0 + lkq * 4);
        float4 bv = *(const float4*)(brow + k0 + lkq * 4);
        As[lkq*4+0][lrow] = av.x; As[lkq*4+1][lrow] = av.y;
        As[lkq*4+2][lrow] = av.z; As[lkq*4+3][lrow] = av.w;
        Bsd[lkq*4+0][lrow] = make_float2(bv.x, bv.x);
        Bsd[lkq*4+1][lrow] = make_float2(bv.y, bv.y);
        Bsd[lkq*4+2][lrow] = make_float2(bv.z, bv.z);
        Bsd[lkq*4+3][lrow] = make_float2(bv.w, bv.w);
        __syncthreads();
        #pragma unroll
        for (int kk = 0; kk < 16; kk++){
            ulonglong2 a   = *(const ulonglong2*)&As[kk][ty * 4];
            ulonglong2 b01 = *(const ulonglong2*)&Bsd[kk][tx * 4];
            ulonglong2 b23 = *(const ulonglong2*)&Bsd[kk][tx * 4 + 2];
            FMA2(acc[0][0], a.x, b01.x); FMA2(acc[0][1], a.y, b01.x);
            FMA2(acc[1][0], a.x, b01.y); FMA2(acc[1][1], a.y, b01.y);
            FMA2(acc[2][0], a.x, b23.x); FMA2(acc[2][1], a.y, b23.x);
            FMA2(acc[3][0], a.x, b23.y); FMA2(acc[3][1], a.y, b23.y);
        }
        __syncthreads();
    }

    float4 bias = *(const float4*)(bih + j0 + tx * 4);
    #pragma unroll
    for (int p = 0; p < 2; p++){
        int m0 = ty * 4 + 2 * p;
        float4 v0, v1;
        v0.x = lo32(acc[0][p]) + bias.x; v0.y = lo32(acc[1][p]) + bias.y;
        v0.z = lo32(acc[2][p]) + bias.z; v0.w = lo32(acc[3][p]) + bias.w;
        v1.x = hi32(acc[0][p]) + bias.x; v1.y = hi32(acc[1][p]) + bias.y;
        v1.z = hi32(acc[2][p]) + bias.z; v1.w = hi32(acc[3][p]) + bias.w;
        *(float4*)&g_gi[(size_t)(t * B_ + m0    ) * H3_ + j0 + tx * 4] = v0;
        *(float4*)&g_gi[(size_t)(t * B_ + m0 + 1) * H3_ + j0 + tx * 4] = v1;
    }
}

// ---------------- one GRU step ----------------
// grid 128 blocks: block owns 8 gate-columns (x3 gates = 24 W_hh rows) x 64 batches.
// 8 warps split K=1024; f32x2 outer product; ordered smem reduction; fused gates.
__global__ __launch_bounds__(256) void step_kernel(const float* __restrict__ Whh,
                                                   const float* __restrict__ bhh,
                                                   int t)
{
    __shared__ __align__(16) float  hs[32][72];        // [k][b]
    __shared__ __align__(16) float2 wsd2[32][26];      // [k][jj] duplicated
    __shared__ float credw[8][12][65];                 // per-warp partials (half of jc range)
    __shared__ float ghs[24][65];                      // reduced gh (+b_hh)

    const float* hin  = (t & 1) ? g_h1 : g_h0;
    float*       hout = (t & 1) ? g_h0 : g_h1;

    const int tid = threadIdx.x;
    const int wp  = tid >> 5;          // warp 0..7
    const int l   = tid & 31;
    const int b0  = (l & 7) * 8;       // 8 batches per lane
    const int cg  = l >> 3;            // col group 0..3 (6 cols each)
    const int c0  = blockIdx.x * 8;

    const int lb  = tid >> 2;          // h loader row
    const int lkq = tid & 3;

    u64 acc[6][4];
    #pragma unroll
    for (int j = 0; j < 6; j++)
        #pragma unroll
        for (int p = 0; p < 4; p++) acc[j][p] = 0ull;

    for (int k0 = 0; k0 < H_; k0 += 32){
        // load h tile transposed
        float4 h0v = *(const float4*)(hin + (size_t)lb * H_ + k0 + lkq * 4);
        float4 h1v = *(const float4*)(hin + (size_t)lb * H_ + k0 + 16 + lkq * 4);
        hs[lkq*4+0][lb] = h0v.x; hs[lkq*4+1][lb] = h0v.y;
        hs[lkq*4+2][lb] = h0v.z; hs[lkq*4+3][lb] = h0v.w;
        hs[16+lkq*4+0][lb] = h1v.x; hs[16+lkq*4+1][lb] = h1v.y;
        hs[16+lkq*4+2][lb] = h1v.z; hs[16+lkq*4+3][lb] = h1v.w;
        // load W_hh tile duplicated: jj 0..7 -> r rows, 8..15 -> z, 16..23 -> n
        #pragma unroll
        for (int i = tid; i < 768; i += 256){
            int kk = i & 31, jj = i >> 5;
            int jglob = (jj >> 3) * H_ + c0 + (jj & 7);
            float wv = Whh[(size_t)jglob * H_ + k0 + kk];
            wsd2[kk][jj] = make_float2(wv, wv);
        }
        __syncthreads();
        #pragma unroll
        for (int q = 0; q < 4; q++){
            int kk = wp * 4 + q;
            ulonglong2 a01 = *(const ulonglong2*)&hs[kk][b0];
            ulonglong2 a23 = *(const ulonglong2*)&hs[kk][b0 + 4];
            ulonglong2 w01 = *(const ulonglong2*)&wsd2[kk][cg * 6];
            ulonglong2 w23 = *(const ulonglong2*)&wsd2[kk][cg * 6 + 2];
            ulonglong2 w45 = *(const ulonglong2*)&wsd2[kk][cg * 6 + 4];
            FMA2(acc[0][0], a01.x, w01.x); FMA2(acc[0][1], a01.y, w01.x);
            FMA2(acc[0][2], a23.x, w01.x); FMA2(acc[0][3], a23.y, w01.x);
            FMA2(acc[1][0], a01.x, w01.y); FMA2(acc[1][1], a01.y, w01.y);
            FMA2(acc[1][2], a23.x, w01.y); FMA2(acc[1][3], a23.y, w01.y);
            FMA2(acc[2][0], a01.x, w23.x); FMA2(acc[2][1], a01.y, w23.x);
            FMA2(acc[2][2], a23.x, w23.x); FMA2(acc[2][3], a23.y, w23.x);
            FMA2(acc[3][0], a01.x, w23.y); FMA2(acc[3][1], a01.y, w23.y);
            FMA2(acc[3][2], a23.x, w23.y); FMA2(acc[3][3], a23.y, w23.y);
            FMA2(acc[4][0], a01.x, w45.x); FMA2(acc[4][1], a01.y, w45.x);
            FMA2(acc[4][2], a23.x, w45.x); FMA2(acc[4][3], a23.y, w45.x);
            FMA2(acc[5][0], a01.x, w45.y); FMA2(acc[5][1], a01.y, w45.y);
            FMA2(acc[5][2], a23.x, w45.y); FMA2(acc[5][3], a23.y, w45.y);
        }
        __syncthreads();
    }

    // deterministic cross-warp reduction, two passes over jc halves
    #pragma unroll
    for (int p = 0; p < 2; p++){
        #pragma unroll
        for (int jc2 = 0; jc2 < 3; jc2++){
            int jc  = p * 3 + jc2;
            int jjA = cg * 3 + jc2;
            #pragma unroll
            for (int bp = 0; bp < 4; bp++){
                u64 v = acc[jc][bp];
                credw[wp][jjA][b0 + 2*bp    ] = lo32(v);
                credw[wp][jjA][b0 + 2*bp + 1] = hi32(v);
            }
        }
        __syncthreads();
        #pragma unroll
        for (int o = tid; o < 768; o += 256){
            int jjA = o >> 6, b = o & 63;
            float s = 0.0f;
            #pragma unroll
            for (int ww = 0; ww < 8; ww++) s += credw[ww][jjA][b];
            int cg2 = jjA / 3, jc2 = jjA % 3;
            int jj = cg2 * 6 + p * 3 + jc2;
            int jglob = (jj >> 3) * H_ + c0 + (jj & 7);
            ghs[jj][b] = s + bhh[jglob];
        }
        __syncthreads();
    }

    // fused gate math + h update
    const float* gib = g_gi + (size_t)t * B_ * H3_;
    #pragma unroll
    for (int o = tid; o < 512; o += 256){
        int b = o >> 3, c = o & 7;
        int col = c0 + c;
        float ghr = ghs[c][b], ghz = ghs[8 + c][b], ghn = ghs[16 + c][b];
        const float* g = gib + (size_t)b * H3_ + col;
        float gir = g[0], giz = g[H_], gin = g[2 * H_];
        float r = sigmoidf_(gir + ghr);
        float z = sigmoidf_(giz + ghz);
        float n = tanhf_(gin + r * ghn);
        float hprev = hin[(size_t)b * H_ + col];
        hout[(size_t)b * H_ + col] = (1.0f - z) * n + z * hprev;
    }
}

// ---------------- logits = h_final @ W_dense^T + b_dense ----------------
__global__ __launch_bounds__(256) void dense_kernel(const float* __restrict__ Wd,
                                                    const float* __restrict__ bd,
                                                    float* __restrict__ out)
{
    __shared__ __align__(16) float  As[16][72];
    __shared__ __align__(16) float2 Bsd[16][66];

    const int tid = threadIdx.x;
    const int tx = tid & 15, ty = tid >> 4;
    const int lrow = tid >> 2, lkq = tid & 3;
    const int j0 = blockIdx.x * 64;

    const float* arow = g_h0 + (size_t)lrow * H_;
    const int jrow = j0 + lrow;
    const bool jok = (jrow < OUT_);
    const float* brow = Wd + (size_t)(jok ? jrow : 0) * H_;

    u64 acc[4][2];
    #pragma unroll
    for (int j = 0; j < 4; j++){ acc[j][0] = 0ull; acc[j][1] = 0ull; }

    for (int k0 = 0; k0 < H_; k0 += 16){
        float4 av = *(const float4*)(arow + k0 + lkq * 4);
        float4 bv = make_float4(0.f, 0.f, 0.f, 0.f);
        if (jok) bv = *(const float4*)(brow + k0 + lkq * 4);
        As[lkq*4+0][lrow] = av.x; As[lkq*4+1][lrow] = av.y;
        As[lkq*4+2][lrow] = av.z; As[lkq*4+3][lrow] = av.w;
        Bsd[lkq*4+0][lrow] = make_float2(bv.x, bv.x);
        Bsd[lkq*4+1][lrow] = make_float2(bv.y, bv.y);
        Bsd[lkq*4+2][lrow] = make_float2(bv.z, bv.z);
        Bsd[lkq*4+3][lrow] = make_float2(bv.w, bv.w);
        __syncthreads();
        #pragma unroll
        for (int kk = 0; kk < 16; kk++){
            ulonglong2 a   = *(const ulonglong2*)&As[kk][ty * 4];
            ulonglong2 b01 = *(const ulonglong2*)&Bsd[kk][tx * 4];
            ulonglong2 b23 = *(const ulonglong2*)&Bsd[kk][tx * 4 + 2];
            FMA2(acc[0][0], a.x, b01.x); FMA2(acc[0][1], a.y, b01.x);
            FMA2(acc[1][0], a.x, b01.y); FMA2(acc[1][1], a.y, b01.y);
            FMA2(acc[2][0], a.x, b23.x); FMA2(acc[2][1], a.y, b23.x);
            FMA2(acc[3][0], a.x, b23.y); FMA2(acc[3][1], a.y, b23.y);
        }
        __syncthreads();
    }

    #pragma unroll
    for (int p = 0; p < 2; p++){
        #pragma unroll
        for (int half = 0; half < 2; half++){
            int m = ty * 4 + 2 * p + half;
            #pragma unroll
            for (int j = 0; j < 4; j++){
                int col = j0 + tx * 4 + j;
                if (col < OUT_){
                    float v = half ? hi32(acc[j][p]) : lo32(acc[j][p]);
                    out[(size_t)m * OUT_ + col] = v + bd[col];
                }
            }
        }
    }
}

// ---------------- in-place row-wise log_softmax ----------------
__global__ __launch_bounds__(256) void lsm_kernel(float* __restrict__ out)
{
    __shared__ float red[256];
    const int tid = threadIdx.x;
    float* row = out + (size_t)blockIdx.x * OUT_;

    float m = -1e30f;
    for (int i = tid; i < OUT_; i += 256) m = fmaxf(m, row[i]);
    red[tid] = m; __syncthreads();
    for (int s = 128; s > 0; s >>= 1){
        if (tid < s) red[tid] = fmaxf(red[tid], red[tid + s]);
        __syncthreads();
    }
    float M = red[0];
    __syncthreads();

    float sm = 0.0f;
    for (int i = tid; i < OUT_; i += 256) sm += expf(row[i] - M);
    red[tid] = sm; __syncthreads();
    for (int s = 128; s > 0; s >>= 1){
        if (tid < s) red[tid] += red[tid + s];
        __syncthreads();
    }
    float L = M + logf(red[0]);
    for (int i = tid; i < OUT_; i += 256) row[i] -= L;
}

// ---------------- launch ----------------
extern "C" void kernel_launch(void* const* d_in, const int* in_sizes, int n_in,
                              void* d_out, int out_size)
{
    const float* x    = (const float*)d_in[0];
    const float* Wih  = (const float*)d_in[1];
    const float* Whh  = (const float*)d_in[2];
    const float* bih  = (const float*)d_in[3];
    const float* bhh  = (const float*)d_in[4];
    const float* Wd   = (const float*)d_in[5];
    const float* bd   = (const float*)d_in[6];
    float* out = (float*)d_out;

    zero_h_kernel<<<64, 1024>>>();
    gi_kernel<<<dim3(48, T_), 256>>>(x, Wih, bih);
    for (int t = 0; t < T_; t++)
        step_kernel<<<128, 256>>>(Whh, bhh, t);
    dense_kernel<<<(OUT_ + 63) / 64, 256>>>(Wd, bd, out);
    lsm_kernel<<<B_, 256>>>(out);
}

// round 3
// speedup vs baseline: 1.7248x; 1.7248x over previous
#include <cuda_runtime.h>
#include <math.h>

#define T_    512
#define B_    64
#define IN_   256
#define H_    1024
#define H3_   3072
#define OUT_  50257
#define NBLK  128

// ---------------- device scratch (no allocations allowed) ----------------
__device__ float g_gi[(size_t)T_ * B_ * H3_];   // [T][B][3H] input gates (+b_ih)
__device__ float g_hT0[H_ * B_];                // h transposed [k][b]
__device__ float g_hT1[H_ * B_];
__device__ unsigned g_bar_count;
__device__ unsigned g_bar_phase;

typedef unsigned long long u64;

// packed f32x2 FMA: acc(lo,hi) += a(lo,hi) * b(lo,hi)
#define FMA2(acc, a, b) asm("fma.rn.f32x2 %0, %1, %2, %0;" : "+l"(acc) : "l"(a), "l"(b))

static __device__ __forceinline__ float lo32(u64 v){ return __uint_as_float((unsigned)(v & 0xffffffffull)); }
static __device__ __forceinline__ float hi32(u64 v){ return __uint_as_float((unsigned)(v >> 32)); }

static __device__ __forceinline__ float sigmoidf_(float x){ return 1.0f / (1.0f + expf(-x)); }
static __device__ __forceinline__ float tanhf_(float x){
    float e = expf(-2.0f * fabsf(x));
    float t = (1.0f - e) / (1.0f + e);
    return copysignf(t, x);
}

// ---------------- init ----------------
__global__ void init_kernel(){
    int i = blockIdx.x * blockDim.x + threadIdx.x;
    if (i < H_ * B_) g_hT0[i] = 0.0f;
    if (i == 0){ g_bar_count = 0u; g_bar_phase = 0u; }
}

// ---------------- GI = in_seq @ W_ih^T + b_ih ----------------
__global__ __launch_bounds__(256) void gi_kernel(const float* __restrict__ x,
                                                 const float* __restrict__ Wih,
                                                 const float* __restrict__ bih)
{
    __shared__ __align__(16) float  As[16][72];    // [k][m] transposed
    __shared__ __align__(16) float2 Bsd[16][66];   // [k][j] duplicated (w,w)

    const int tid = threadIdx.x;
    const int tx = tid & 15, ty = tid >> 4;
    const int lrow = tid >> 2, lkq = tid & 3;

    const int t  = blockIdx.y;
    const int j0 = blockIdx.x * 64;

    const float* arow = x   + (size_t)lrow * (T_ * IN_) + (size_t)t * IN_;
    const float* brow = Wih + (size_t)(j0 + lrow) * IN_;

    u64 acc[4][2];
    #pragma unroll
    for (int j = 0; j < 4; j++){ acc[j][0] = 0ull; acc[j][1] = 0ull; }

    for (int k0 = 0; k0 < IN_; k0 += 16){
        float4 av = *(const float4*)(arow + k0 + lkq * 4);
        float4 bv = *(const float4*)(brow + k0 + lkq * 4);
        As[lkq*4+0][lrow] = av.x; As[lkq*4+1][lrow] = av.y;
        As[lkq*4+2][lrow] = av.z; As[lkq*4+3][lrow] = av.w;
        Bsd[lkq*4+0][lrow] = make_float2(bv.x, bv.x);
        Bsd[lkq*4+1][lrow] = make_float2(bv.y, bv.y);
        Bsd[lkq*4+2][lrow] = make_float2(bv.z, bv.z);
        Bsd[lkq*4+3][lrow] = make_float2(bv.w, bv.w);
        __syncthreads();
        #pragma unroll
        for (int kk = 0; kk < 16; kk++){
            ulonglong2 a   = *(const ulonglong2*)&As[kk][ty * 4];
            ulonglong2 b01 = *(const ulonglong2*)&Bsd[kk][tx * 4];
            ulonglong2 b23 = *(const ulonglong2*)&Bsd[kk][tx * 4 + 2];
            FMA2(acc[0][0], a.x, b01.x); FMA2(acc[0][1], a.y, b01.x);
            FMA2(acc[1][0], a.x, b01.y); FMA2(acc[1][1], a.y, b01.y);
            FMA2(acc[2][0], a.x, b23.x); FMA2(acc[2][1], a.y, b23.x);
            FMA2(acc[3][0], a.x, b23.y); FMA2(acc[3][1], a.y, b23.y);
        }
        __syncthreads();
    }

    float4 bias = *(const float4*)(bih + j0 + tx * 4);
    #pragma unroll
    for (int p = 0; p < 2; p++){
        int m0 = ty * 4 + 2 * p;
        float4 v0, v1;
        v0.x = lo32(acc[0][p]) + bias.x; v0.y = lo32(acc[1][p]) + bias.y;
        v0.z = lo32(acc[2][p]) + bias.z; v0.w = lo32(acc[3][p]) + bias.w;
        v1.x = hi32(acc[0][p]) + bias.x; v1.y = hi32(acc[1][p]) + bias.y;
        v1.z = hi32(acc[2][p]) + bias.z; v1.w = hi32(acc[3][p]) + bias.w;
        *(float4*)&g_gi[(size_t)(t * B_ + m0    ) * H3_ + j0 + tx * 4] = v0;
        *(float4*)&g_gi[(size_t)(t * B_ + m0 + 1) * H3_ + j0 + tx * 4] = v1;
    }
}

// ---------------- persistent GRU recurrence ----------------
__device__ __forceinline__ void load_h(ulonglong2* A, ulonglong2* Bv, const float* hb, int kbase)
{
    #pragma unroll
    for (int q = 0; q < 4; q++){
        A[q]  = *(const ulonglong2*)(hb + (size_t)(kbase + q) * B_);
        Bv[q] = *(const ulonglong2*)(hb + (size_t)(kbase + q) * B_ + 4);
    }
}

__device__ __forceinline__ void fma_tile(u64 (&acc)[6][4], const ulonglong2* A, const ulonglong2* Bv,
                                         const float2* __restrict__ wdup, int kbase, int cg)
{
    #pragma unroll
    for (int q = 0; q < 4; q++){
        const float2* wr = wdup + (size_t)(kbase + q) * 24 + cg * 6;
        ulonglong2 w01 = *(const ulonglong2*)(wr);
        ulonglong2 w23 = *(const ulonglong2*)(wr + 2);
        ulonglong2 w45 = *(const ulonglong2*)(wr + 4);
        ulonglong2 a01 = A[q], a23 = Bv[q];
        FMA2(acc[0][0], a01.x, w01.x); FMA2(acc[0][1], a01.y, w01.x);
        FMA2(acc[0][2], a23.x, w01.x); FMA2(acc[0][3], a23.y, w01.x);
        FMA2(acc[1][0], a01.x, w01.y); FMA2(acc[1][1], a01.y, w01.y);
        FMA2(acc[1][2], a23.x, w01.y); FMA2(acc[1][3], a23.y, w01.y);
        FMA2(acc[2][0], a01.x, w23.x); FMA2(acc[2][1], a01.y, w23.x);
        FMA2(acc[2][2], a23.x, w23.x); FMA2(acc[2][3], a23.y, w23.x);
        FMA2(acc[3][0], a01.x, w23.y); FMA2(acc[3][1], a01.y, w23.y);
        FMA2(acc[3][2], a23.x, w23.y); FMA2(acc[3][3], a23.y, w23.y);
        FMA2(acc[4][0], a01.x, w45.x); FMA2(acc[4][1], a01.y, w45.x);
        FMA2(acc[4][2], a23.x, w45.x); FMA2(acc[4][3], a23.y, w45.x);
        FMA2(acc[5][0], a01.x, w45.y); FMA2(acc[5][1], a01.y, w45.y);
        FMA2(acc[5][2], a23.x, w45.y); FMA2(acc[5][3], a23.y, w45.y);
    }
}

__global__ __launch_bounds__(256, 1) void gru_persist(const float* __restrict__ Whh,
                                                      const float* __restrict__ bhh)
{
    extern __shared__ __align__(16) char smem_raw[];
    float2* wdup = (float2*)smem_raw;                                  // [1024][24] dup (w,w)
    float*  credw = (float*)(smem_raw + (size_t)H_ * 24 * sizeof(float2)); // [8][12][65]
    float*  ghs   = credw + 8 * 12 * 65;                               // [24][65]
    __shared__ float bh_s[24];

    const int tid = threadIdx.x;
    const int wp  = tid >> 5;
    const int l   = tid & 31;
    const int b0  = (l & 7) * 8;
    const int cg  = l >> 3;
    const int c0  = blockIdx.x * 8;

    // ---- one-time: load this block's 24 W_hh rows, duplicated ----
    #pragma unroll 1
    for (int jj = 0; jj < 24; jj++){
        int jglob = (jj >> 3) * H_ + c0 + (jj & 7);
        const float* wr = Whh + (size_t)jglob * H_;
        for (int k = tid; k < H_; k += 256){
            float w = wr[k];
            wdup[(size_t)k * 24 + jj] = make_float2(w, w);
        }
    }
    if (tid < 24){
        int jglob = (tid >> 3) * H_ + c0 + (tid & 7);
        bh_s[tid] = bhh[jglob];
    }
    __syncthreads();

    #pragma unroll 1
    for (int t = 0; t < T_; t++){
        const float* hin  = (t & 1) ? g_hT1 : g_hT0;
        float*       hout = (t & 1) ? g_hT0 : g_hT1;

        // prefetch gi + hprev for the gate phase (consumed at step end)
        float pre_gir[2], pre_giz[2], pre_gin[2], pre_h[2];
        const float* gib = g_gi + (size_t)t * B_ * H3_;
        #pragma unroll
        for (int u = 0; u < 2; u++){
            int o = tid + u * 256;
            int b = o >> 3, c = o & 7, col = c0 + c;
            const float* g = gib + (size_t)b * H3_ + col;
            pre_gir[u] = g[0]; pre_giz[u] = g[H_]; pre_gin[u] = g[2 * H_];
            pre_h[u]   = hin[(size_t)col * B_ + b];
        }

        u64 acc[6][4];
        #pragma unroll
        for (int j = 0; j < 6; j++)
            #pragma unroll
            for (int p = 0; p < 4; p++) acc[j][p] = 0ull;

        const float* hb = hin + b0;

        // K loop, double-buffered h loads, no barriers
        ulonglong2 cA[4], cB[4], nA[4], nB[4];
        load_h(cA, cB, hb, wp * 4);
        #pragma unroll 1
        for (int k0 = 0; k0 < H_; k0 += 64){
            load_h(nA, nB, hb, k0 + 32 + wp * 4);
            fma_tile(acc, cA, cB, wdup, k0 + wp * 4, cg);
            if (k0 + 64 < H_) load_h(cA, cB, hb, k0 + 64 + wp * 4);
            fma_tile(acc, nA, nB, wdup, k0 + 32 + wp * 4, cg);
        }

        // deterministic cross-warp reduction, two passes
        #pragma unroll
        for (int p = 0; p < 2; p++){
            #pragma unroll
            for (int jc2 = 0; jc2 < 3; jc2++){
                int jc  = p * 3 + jc2;
                int jjA = cg * 3 + jc2;
                #pragma unroll
                for (int bp = 0; bp < 4; bp++){
                    u64 v = acc[jc][bp];
                    credw[((size_t)wp * 12 + jjA) * 65 + b0 + 2*bp    ] = lo32(v);
                    credw[((size_t)wp * 12 + jjA) * 65 + b0 + 2*bp + 1] = hi32(v);
                }
            }
            __syncthreads();
            #pragma unroll
            for (int o = tid; o < 768; o += 256){
                int jjA = o >> 6, b = o & 63;
                float s = 0.0f;
                #pragma unroll
                for (int ww = 0; ww < 8; ww++) s += credw[((size_t)ww * 12 + jjA) * 65 + b];
                int cg2 = jjA / 3, jc2 = jjA % 3;
                int jj = cg2 * 6 + p * 3 + jc2;
                ghs[(size_t)jj * 65 + b] = s + bh_s[jj];
            }
            __syncthreads();
        }

        // fused gate math + transposed h update
        #pragma unroll
        for (int u = 0; u < 2; u++){
            int o = tid + u * 256;
            int b = o >> 3, c = o & 7, col = c0 + c;
            float ghr = ghs[(size_t)(c     ) * 65 + b];
            float ghz = ghs[(size_t)(8  + c) * 65 + b];
            float ghn = ghs[(size_t)(16 + c) * 65 + b];
            float r = sigmoidf_(pre_gir[u] + ghr);
            float z = sigmoidf_(pre_giz[u] + ghz);
            float n = tanhf_(pre_gin[u] + r * ghn);
            hout[(size_t)col * B_ + b] = (1.0f - z) * n + z * pre_h[u];
        }

        // ---- grid-wide barrier (release/acquire) ----
        __threadfence();
        __syncthreads();
        if (tid == 0){
            unsigned arr;
            asm volatile("atom.acq_rel.gpu.global.add.u32 %0, [%1], %2;"
                         : "=r"(arr) : "l"(&g_bar_count), "r"(1u) : "memory");
            unsigned target = (unsigned)t + 1u;
            if (arr == NBLK - 1){
                atomicExch(&g_bar_count, 0u);
                __threadfence();
                asm volatile("st.release.gpu.global.u32 [%0], %1;"
                             :: "l"(&g_bar_phase), "r"(target) : "memory");
            } else {
                unsigned pcur;
                do {
                    asm volatile("ld.acquire.gpu.global.u32 %0, [%1];"
                                 : "=r"(pcur) : "l"(&g_bar_phase) : "memory");
                } while (pcur < target);
            }
        }
        __syncthreads();
    }
}

// ---------------- logits = h_final @ W_dense^T + b_dense (h transposed) ----------------
__global__ __launch_bounds__(256) void dense_kernel(const float* __restrict__ Wd,
                                                    const float* __restrict__ bd,
                                                    float* __restrict__ out)
{
    __shared__ __align__(16) float  As[16][72];    // [k][b]
    __shared__ __align__(16) float2 Bsd[16][66];

    const int tid = threadIdx.x;
    const int tx = tid & 15, ty = tid >> 4;
    const int lrow = tid >> 2, lkq = tid & 3;
    const int kk_ld = tid >> 4;          // 0..15
    const int bq_ld = (tid & 15) * 4;    // 0..60
    const int j0 = blockIdx.x * 64;

    const int jrow = j0 + lrow;
    const bool jok = (jrow < OUT_);
    const float* brow = Wd + (size_t)(jok ? jrow : 0) * H_;

    u64 acc[4][2];
    #pragma unroll
    for (int j = 0; j < 4; j++){ acc[j][0] = 0ull; acc[j][1] = 0ull; }

    for (int k0 = 0; k0 < H_; k0 += 16){
        float4 av = *(const float4*)(g_hT0 + (size_t)(k0 + kk_ld) * B_ + bq_ld);
        float4 bv = make_float4(0.f, 0.f, 0.f, 0.f);
        if (jok) bv = *(const float4*)(brow + k0 + lkq * 4);
        *(float4*)&As[kk_ld][bq_ld] = av;
        Bsd[lkq*4+0][lrow] = make_float2(bv.x, bv.x);
        Bsd[lkq*4+1][lrow] = make_float2(bv.y, bv.y);
        Bsd[lkq*4+2][lrow] = make_float2(bv.z, bv.z);
        Bsd[lkq*4+3][lrow] = make_float2(bv.w, bv.w);
        __syncthreads();
        #pragma unroll
        for (int kk = 0; kk < 16; kk++){
            ulonglong2 a   = *(const ulonglong2*)&As[kk][ty * 4];
            ulonglong2 b01 = *(const ulonglong2*)&Bsd[kk][tx * 4];
            ulonglong2 b23 = *(const ulonglong2*)&Bsd[kk][tx * 4 + 2];
            FMA2(acc[0][0], a.x, b01.x); FMA2(acc[0][1], a.y, b01.x);
            FMA2(acc[1][0], a.x, b01.y); FMA2(acc[1][1], a.y, b01.y);
            FMA2(acc[2][0], a.x, b23.x); FMA2(acc[2][1], a.y, b23.x);
            FMA2(acc[3][0], a.x, b23.y); FMA2(acc[3][1], a.y, b23.y);
        }
        __syncthreads();
    }

    #pragma unroll
    for (int p = 0; p < 2; p++){
        #pragma unroll
        for (int half = 0; half < 2; half++){
            int m = ty * 4 + 2 * p + half;
            #pragma unroll
            for (int j = 0; j < 4; j++){
                int col = j0 + tx * 4 + j;
                if (col < OUT_){
                    float v = half ? hi32(acc[j][p]) : lo32(acc[j][p]);
                    out[(size_t)m * OUT_ + col] = v + bd[col];
                }
            }
        }
    }
}

// ---------------- in-place row-wise log_softmax ----------------
__global__ __launch_bounds__(256) void lsm_kernel(float* __restrict__ out)
{
    __shared__ float red[256];
    const int tid = threadIdx.x;
    float* row = out + (size_t)blockIdx.x * OUT_;

    float m = -1e30f;
    for (int i = tid; i < OUT_; i += 256) m = fmaxf(m, row[i]);
    red[tid] = m; __syncthreads();
    for (int s = 128; s > 0; s >>= 1){
        if (tid < s) red[tid] = fmaxf(red[tid], red[tid + s]);
        __syncthreads();
    }
    float M = red[0];
    __syncthreads();

    float sm = 0.0f;
    for (int i = tid; i < OUT_; i += 256) sm += expf(row[i] - M);
    red[tid] = sm; __syncthreads();
    for (int s = 128; s > 0; s >>= 1){
        if (tid < s) red[tid] += red[tid + s];
        __syncthreads();
    }
    float L = M + logf(red[0]);
    for (int i = tid; i < OUT_; i += 256) row[i] -= L;
}

// ---------------- launch ----------------
extern "C" void kernel_launch(void* const* d_in, const int* in_sizes, int n_in,
                              void* d_out, int out_size)
{
    const float* x    = (const float*)d_in[0];
    const float* Wih  = (const float*)d_in[1];
    const float* Whh  = (const float*)d_in[2];
    const float* bih  = (const float*)d_in[3];
    const float* bhh  = (const float*)d_in[4];
    const float* Wd   = (const float*)d_in[5];
    const float* bd   = (const float*)d_in[6];
    float* out = (float*)d_out;

    const size_t smem_bytes = (size_t)H_ * 24 * sizeof(float2)   // wdup 196608
                            + 8 * 12 * 65 * sizeof(float)        // credw  24960
                            + 24 * 65 * sizeof(float);           // ghs     6240
    cudaFuncSetAttribute(gru_persist, cudaFuncAttributeMaxDynamicSharedMemorySize,
                         (int)smem_bytes);

    init_kernel<<<64, 1024>>>();
    gi_kernel<<<dim3(48, T_), 256>>>(x, Wih, bih);
    gru_persist<<<NBLK, 256, smem_bytes>>>(Whh, bhh);
    dense_kernel<<<(OUT_ + 63) / 64, 256>>>(Wd, bd, out);
    lsm_kernel<<<B_, 256>>>(out);
}

// round 8
// speedup vs baseline: 1.8894x; 1.0954x over previous
#include <cuda_runtime.h>
#include <math.h>
#include <cstdint>

#define T_    512
#define B_    64
#define IN_   256
#define H_    1024
#define H3_   3072
#define OUT_  50257

#define NB    64          // persistent blocks; block owns 16 gate-columns
#define WPAD  1028        // padded word stride per warp-slice in reduction smem

// ---------------- device scratch ----------------
__device__ float g_gi[(size_t)T_ * B_ * H3_];    // [T][B][3H]
__device__ float g_hT0[H_ * B_];                 // h fp32 [col][b]
__device__ uint4 g_wfrag[64 * 3 * 64 * 32 * 2];  // W frags: [(blk*3+mt)*64+ktg][lane][hi|lo]
__device__ uint4 g_hfrag[8 * 64 * 32];           // h frags: [(nt*64+ktg)*32+lane] {hi b0,b1, lo b0,b1}
__device__ float g_bhh[H3_];
__device__ unsigned g_bar_count;
__device__ unsigned g_bar_phase;

typedef unsigned long long u64;

#define FMA2(acc, a, b) asm("fma.rn.f32x2 %0, %1, %2, %0;" : "+l"(acc) : "l"(a), "l"(b))

static __device__ __forceinline__ float lo32(u64 v){ return __uint_as_float((unsigned)(v & 0xffffffffull)); }
static __device__ __forceinline__ float hi32(u64 v){ return __uint_as_float((unsigned)(v >> 32)); }
static __device__ __forceinline__ float sigmoidf_(float x){ return 1.0f / (1.0f + expf(-x)); }
static __device__ __forceinline__ float tanhf_(float x){
    float e = expf(-2.0f * fabsf(x));
    float t = (1.0f - e) / (1.0f + e);
    return copysignf(t, x);
}

// manual bf16 round-to-nearest-even
static __device__ __forceinline__ unsigned f2bf(float f){
    unsigned u = __float_as_uint(f);
    unsigned r = u + 0x7FFFu + ((u >> 16) & 1u);
    return (r >> 16) & 0xFFFFu;
}
static __device__ __forceinline__ float bf2f(unsigned s){
    return __uint_as_float(s << 16);
}
static __device__ __forceinline__ unsigned pack_bf2(float a, float b){
    return f2bf(a) | (f2bf(b) << 16);
}

// mma.sync bf16: D = A(16x16) * B(16x8) + D  (base ISA, compiles for compute_103)
#define MMA_BF16(C, A, b0v, b1v) \
    asm volatile("mma.sync.aligned.m16n8k16.row.col.f32.bf16.bf16.f32 " \
        "{%0,%1,%2,%3}, {%4,%5,%6,%7}, {%8,%9}, {%0,%1,%2,%3};" \
        : "+f"((C)[0]), "+f"((C)[1]), "+f"((C)[2]), "+f"((C)[3]) \
        : "r"((A).x), "r"((A).y), "r"((A).z), "r"((A).w), "r"(b0v), "r"(b1v))

// ---------------- init ----------------
__global__ void init_kernel(){
    int i = blockIdx.x * blockDim.x + threadIdx.x;
    if (i < H_ * B_) g_hT0[i] = 0.0f;
    if (i < 8 * 64 * 32) g_hfrag[i] = make_uint4(0u, 0u, 0u, 0u);
    if (i == 0){ g_bar_count = 0u; g_bar_phase = 0u; }
}

__global__ void bhh_copy_kernel(const float* __restrict__ bhh){
    int i = blockIdx.x * 256 + threadIdx.x;
    if (i < H3_) g_bhh[i] = bhh[i];
}

// ---------------- W_hh -> fragment layout (hi/lo bf16 planes) ----------------
__global__ void wfrag_kernel(const float* __restrict__ Whh){
    int gid = blockIdx.x * 256 + threadIdx.x;   // 1536 blocks x 256 = 393216
    int lane = gid & 31;
    int tile = gid >> 5;                        // 12288 tiles
    if (tile >= 64 * 3 * 64) return;
    int ktg = tile & 63;
    int mt  = (tile >> 6) % 3;
    int blk = tile / 192;
    int c0  = blk * 16;
    int row0 = mt * H_ + c0;
    int j = lane >> 2;
    int k = ktg * 16 + (lane & 3) * 2;

    const float* W = Whh;
    float w00 = W[(size_t)(row0 + j    ) * H_ + k    ];
    float w01 = W[(size_t)(row0 + j    ) * H_ + k + 1];
    float w10 = W[(size_t)(row0 + j + 8) * H_ + k    ];
    float w11 = W[(size_t)(row0 + j + 8) * H_ + k + 1];
    float w02 = W[(size_t)(row0 + j    ) * H_ + k + 8];
    float w03 = W[(size_t)(row0 + j    ) * H_ + k + 9];
    float w12 = W[(size_t)(row0 + j + 8) * H_ + k + 8];
    float w13 = W[(size_t)(row0 + j + 8) * H_ + k + 9];

    uint4 hi, lo;
    hi.x = pack_bf2(w00, w01); hi.y = pack_bf2(w10, w11);
    hi.z = pack_bf2(w02, w03); hi.w = pack_bf2(w12, w13);
    lo.x = pack_bf2(w00 - bf2f(f2bf(w00)), w01 - bf2f(f2bf(w01)));
    lo.y = pack_bf2(w10 - bf2f(f2bf(w10)), w11 - bf2f(f2bf(w11)));
    lo.z = pack_bf2(w02 - bf2f(f2bf(w02)), w03 - bf2f(f2bf(w03)));
    lo.w = pack_bf2(w12 - bf2f(f2bf(w12)), w13 - bf2f(f2bf(w13)));

    g_wfrag[(size_t)tile * 64 + lane * 2    ] = hi;
    g_wfrag[(size_t)tile * 64 + lane * 2 + 1] = lo;
}

// ---------------- GI = in_seq @ W_ih^T + b_ih (unchanged, passing form) ----------------
__global__ __launch_bounds__(256) void gi_kernel(const float* __restrict__ x,
                                                 const float* __restrict__ Wih,
                                                 const float* __restrict__ bih)
{
    __shared__ __align__(16) float  As[16][72];
    __shared__ __align__(16) float2 Bsd[16][66];

    const int tid = threadIdx.x;
    const int tx = tid & 15;
    const int ty = tid >> 4;
    const int lrow = tid >> 2;
    const int lkq = tid & 3;
    const int t  = blockIdx.y;
    const int j0 = blockIdx.x * 64;

    const float* arow = x   + (size_t)lrow * (T_ * IN_) + (size_t)t * IN_;
    const float* brow = Wih + (size_t)(j0 + lrow) * IN_;

    u64 acc[4][2];
    #pragma unroll
    for (int j = 0; j < 4; j++){ acc[j][0] = 0ull; acc[j][1] = 0ull; }

    for (int k0 = 0; k0 < IN_; k0 += 16){
        float4 av = *(const float4*)(arow + k0 + lkq * 4);
        float4 bv = *(const float4*)(brow + k0 + lkq * 4);
        As[lkq*4+0][lrow] = av.x; As[lkq*4+1][lrow] = av.y;
        As[lkq*4+2][lrow] = av.z; As[lkq*4+3][lrow] = av.w;
        Bsd[lkq*4+0][lrow] = make_float2(bv.x, bv.x);
        Bsd[lkq*4+1][lrow] = make_float2(bv.y, bv.y);
        Bsd[lkq*4+2][lrow] = make_float2(bv.z, bv.z);
        Bsd[lkq*4+3][lrow] = make_float2(bv.w, bv.w);
        __syncthreads();
        #pragma unroll
        for (int kk = 0; kk < 16; kk++){
            ulonglong2 a   = *(const ulonglong2*)&As[kk][ty * 4];
            ulonglong2 b01 = *(const ulonglong2*)&Bsd[kk][tx * 4];
            ulonglong2 b23 = *(const ulonglong2*)&Bsd[kk][tx * 4 + 2];
            FMA2(acc[0][0], a.x, b01.x); FMA2(acc[0][1], a.y, b01.x);
            FMA2(acc[1][0], a.x, b01.y); FMA2(acc[1][1], a.y, b01.y);
            FMA2(acc[2][0], a.x, b23.x); FMA2(acc[2][1], a.y, b23.x);
            FMA2(acc[3][0], a.x, b23.y); FMA2(acc[3][1], a.y, b23.y);
        }
        __syncthreads();
    }

    float4 bias = *(const float4*)(bih + j0 + tx * 4);
    #pragma unroll
    for (int p = 0; p < 2; p++){
        int m0 = ty * 4 + 2 * p;
        float4 v0;
        float4 v1;
        v0.x = lo32(acc[0][p]) + bias.x; v0.y = lo32(acc[1][p]) + bias.y;
        v0.z = lo32(acc[2][p]) + bias.z; v0.w = lo32(acc[3][p]) + bias.w;
        v1.x = hi32(acc[0][p]) + bias.x; v1.y = hi32(acc[1][p]) + bias.y;
        v1.z = hi32(acc[2][p]) + bias.z; v1.w = hi32(acc[3][p]) + bias.w;
        *(float4*)&g_gi[(size_t)(t * B_ + m0    ) * H3_ + j0 + tx * 4] = v0;
        *(float4*)&g_gi[(size_t)(t * B_ + m0 + 1) * H3_ + j0 + tx * 4] = v1;
    }
}

// ---------------- grid-wide barrier ----------------
static __device__ __forceinline__ void grid_bar(int tid, unsigned target){
    __threadfence();
    __syncthreads();
    if (tid == 0){
        unsigned arr;
        asm volatile("atom.acq_rel.gpu.global.add.u32 %0, [%1], %2;"
                     : "=r"(arr) : "l"(&g_bar_count), "r"(1u) : "memory");
        if (arr == NB - 1){
            atomicExch(&g_bar_count, 0u);
            __threadfence();
            asm volatile("st.release.gpu.global.u32 [%0], %1;"
                         :: "l"(&g_bar_phase), "r"(target) : "memory");
        } else {
            unsigned pcur;
            do {
                asm volatile("ld.acquire.gpu.global.u32 %0, [%1];"
                             : "=r"(pcur) : "l"(&g_bar_phase) : "memory");
            } while (pcur < target);
        }
    }
    __syncthreads();
}

// ---------------- persistent HMMA recurrence ----------------
__global__ __launch_bounds__(256, 1) void gru_mma()
{
    extern __shared__ float red[];   // [3 gates][8 warps][WPAD words]

    const int tid = threadIdx.x;
    const int w   = tid >> 5;        // warp 0..7 owns k-tiles w, w+8, ..., w+56
    const int l   = tid & 31;
    const int blk = blockIdx.x;
    const int c0  = blk * 16;

    // gate-phase ownership: thread -> (col j, batches n4..n4+3)
    const int j  = tid >> 4;         // 0..15
    const int n4 = (tid & 15) * 4;

    const float bhr = g_bhh[c0 + j];
    const float bhz = g_bhh[H_ + c0 + j];
    const float bhn = g_bhh[2 * H_ + c0 + j];

    // per-warp W-frag bases (A side)
    const uint4* wf = g_wfrag;

    unsigned bar_t = 0;

    #pragma unroll 1
    for (int t = 0; t < T_; t++){
        // prefetch gi + h_old for gate phase
        const float* gib = g_gi + (size_t)t * (B_ * H3_);
        float gir[4], giz[4], gin[4];
        #pragma unroll
        for (int nn = 0; nn < 4; nn++){
            const float* g = gib + (size_t)(n4 + nn) * H3_ + c0 + j;
            gir[nn] = g[0]; giz[nn] = g[H_]; gin[nn] = g[2 * H_];
        }
        float4 hold4 = *(const float4*)&g_hT0[(size_t)(c0 + j) * B_ + n4];

        // ---- MMA phase: C[3 gates][8 n-tiles][4] over this warp's k-tiles ----
        float C[3][8][4];
        #pragma unroll
        for (int mt = 0; mt < 3; mt++)
            #pragma unroll
            for (int nt = 0; nt < 8; nt++)
                #pragma unroll
                for (int r = 0; r < 4; r++) C[mt][nt][r] = 0.0f;

        #pragma unroll 1
        for (int kt8 = 0; kt8 < 8; kt8++){
            const int ktg = kt8 * 8 + w;
            // A fragments (W hi/lo), per-block private, L1-cacheable
            uint4 Ah[3], Al[3];
            #pragma unroll
            for (int mt = 0; mt < 3; mt++){
                size_t ti = ((size_t)(blk * 3 + mt) * 64 + ktg) * 64 + l * 2;
                Ah[mt] = wf[ti];
                Al[mt] = wf[ti + 1];
            }
            // B fragments (h hi/lo), cross-SM data -> L2-only loads
            uint4 Bv[8];
            #pragma unroll
            for (int nt = 0; nt < 8; nt++)
                Bv[nt] = __ldcg(&g_hfrag[(size_t)(nt * 64 + ktg) * 32 + l]);

            #pragma unroll
            for (int mt = 0; mt < 3; mt++){
                #pragma unroll
                for (int nt = 0; nt < 8; nt++){
                    MMA_BF16(C[mt][nt], Ah[mt], Bv[nt].x, Bv[nt].y);  // Wh*Hh
                    MMA_BF16(C[mt][nt], Ah[mt], Bv[nt].z, Bv[nt].w);  // Wh*Hl
                    MMA_BF16(C[mt][nt], Al[mt], Bv[nt].x, Bv[nt].y);  // Wl*Hh
                }
            }
        }

        // ---- store partials to padded smem (conflict-free STS.128) ----
        #pragma unroll
        for (int mt = 0; mt < 3; mt++){
            #pragma unroll
            for (int nt = 0; nt < 8; nt++){
                int wordu = (mt * 8 + w) * WPAD + (nt * 32 + l) * 4;
                *(float4*)&red[wordu] = make_float4(C[mt][nt][0], C[mt][nt][1],
                                                    C[mt][nt][2], C[mt][nt][3]);
            }
        }
        __syncthreads();

        // ---- cross-warp reduce + fused gates + h update ----
        float hnew[4];
        #pragma unroll
        for (int nn = 0; nn < 4; nn++){
            int n   = n4 + nn;
            int nt  = n >> 3;
            int lp  = (j & 7) * 4 + ((n & 7) >> 1);
            int rp  = ((j >> 3) << 1) + (n & 1);
            int base = (nt * 32 + lp) * 4 + rp;
            float gh[3];
            #pragma unroll
            for (int g = 0; g < 3; g++){
                float s = 0.0f;
                #pragma unroll
                for (int wv = 0; wv < 8; wv++)
                    s += red[(g * 8 + wv) * WPAD + base];
                gh[g] = s;
            }
            float hold = (nn == 0) ? hold4.x : (nn == 1) ? hold4.y
                       : (nn == 2) ? hold4.z : hold4.w;
            float r = sigmoidf_(gir[nn] + gh[0] + bhr);
            float z = sigmoidf_(giz[nn] + gh[1] + bhz);
            float nv = tanhf_(gin[nn] + r * (gh[2] + bhn));
            hnew[nn] = (1.0f - z) * nv + z * hold;
        }

        // fp32 master
        *(float4*)&g_hT0[(size_t)(c0 + j) * B_ + n4] =
            make_float4(hnew[0], hnew[1], hnew[2], hnew[3]);

        // bf16 hi/lo fragment planes (B operand for next step)
        unsigned short* hfu = (unsigned short*)g_hfrag;
        int word = (j >> 3);            // 0: b0 (k0-7), 1: b1 (k8-15)
        #pragma unroll
        for (int nn = 0; nn < 4; nn++){
            int n  = n4 + nn;
            int nt = n >> 3;
            int lb = (n & 7) * 4 + ((j & 7) >> 1);
            size_t idx16 = ((size_t)(nt * 64 + blk) * 32 + lb) * 8;
            unsigned hb = f2bf(hnew[nn]);
            unsigned lbv = f2bf(hnew[nn] - bf2f(hb));
            hfu[idx16 + word * 2 + (j & 1)]     = (unsigned short)hb;
            hfu[idx16 + 4 + word * 2 + (j & 1)] = (unsigned short)lbv;
        }

        bar_t += 1u;
        grid_bar(tid, bar_t);
    }
}

// ---------------- logits = h_final @ W_dense^T + b_dense ----------------
__global__ __launch_bounds__(256) void dense_kernel(const float* __restrict__ Wd,
                                                    const float* __restrict__ bd,
                                                    float* __restrict__ out)
{
    __shared__ __align__(16) float  As[16][72];
    __shared__ __align__(16) float2 Bsd[16][66];

    const int tid = threadIdx.x;
    const int tx = tid & 15;
    const int ty = tid >> 4;
    const int lrow = tid >> 2;
    const int lkq = tid & 3;
    const int kk_ld = tid >> 4;
    const int bq_ld = (tid & 15) * 4;
    const int j0 = blockIdx.x * 64;

    const int jrow = j0 + lrow;
    const bool jok = (jrow < OUT_);
    const float* brow = Wd + (size_t)(jok ? jrow : 0) * H_;

    u64 acc[4][2];
    #pragma unroll
    for (int j = 0; j < 4; j++){ acc[j][0] = 0ull; acc[j][1] = 0ull; }

    for (int k0 = 0; k0 < H_; k0 += 16){
        float4 av = *(const float4*)(g_hT0 + (size_t)(k0 + kk_ld) * B_ + bq_ld);
        float4 bv = make_float4(0.f, 0.f, 0.f, 0.f);
        if (jok) bv = *(const float4*)(brow + k0 + lkq * 4);
        *(float4*)&As[kk_ld][bq_ld] = av;
        Bsd[lkq*4+0][lrow] = make_float2(bv.x, bv.x);
        Bsd[lkq*4+1][lrow] = make_float2(bv.y, bv.y);
        Bsd[lkq*4+2][lrow] = make_float2(bv.z, bv.z);
        Bsd[lkq*4+3][lrow] = make_float2(bv.w, bv.w);
        __syncthreads();
        #pragma unroll
        for (int kk = 0; kk < 16; kk++){
            ulonglong2 a   = *(const ulonglong2*)&As[kk][ty * 4];
            ulonglong2 b01 = *(const ulonglong2*)&Bsd[kk][tx * 4];
            ulonglong2 b23 = *(const ulonglong2*)&Bsd[kk][tx * 4 + 2];
            FMA2(acc[0][0], a.x, b01.x); FMA2(acc[0][1], a.y, b01.x);
            FMA2(acc[1][0], a.x, b01.y); FMA2(acc[1][1], a.y, b01.y);
            FMA2(acc[2][0], a.x, b23.x); FMA2(acc[2][1], a.y, b23.x);
            FMA2(acc[3][0], a.x, b23.y); FMA2(acc[3][1], a.y, b23.y);
        }
        __syncthreads();
    }

    #pragma unroll
    for (int p = 0; p < 2; p++){
        #pragma unroll
        for (int half = 0; half < 2; half++){
            int m = ty * 4 + 2 * p + half;
            #pragma unroll
            for (int jj = 0; jj < 4; jj++){
                int col = j0 + tx * 4 + jj;
                if (col < OUT_){
                    float v = half ? hi32(acc[jj][p]) : lo32(acc[jj][p]);
                    out[(size_t)m * OUT_ + col] = v + bd[col];
                }
            }
        }
    }
}

// ---------------- in-place row-wise log_softmax ----------------
__global__ __launch_bounds__(256) void lsm_kernel(float* __restrict__ out)
{
    __shared__ float red[256];
    const int tid = threadIdx.x;
    float* row = out + (size_t)blockIdx.x * OUT_;

    float m = -1e30f;
    for (int i = tid; i < OUT_; i += 256) m = fmaxf(m, row[i]);
    red[tid] = m; __syncthreads();
    for (int s = 128; s > 0; s >>= 1){
        if (tid < s) red[tid] = fmaxf(red[tid], red[tid + s]);
        __syncthreads();
    }
    float M = red[0];
    __syncthreads();

    float sm = 0.0f;
    for (int i = tid; i < OUT_; i += 256) sm += expf(row[i] - M);
    red[tid] = sm; __syncthreads();
    for (int s = 128; s > 0; s >>= 1){
        if (tid < s) red[tid] += red[tid + s];
        __syncthreads();
    }
    float L = M + logf(red[0]);
    for (int i = tid; i < OUT_; i += 256) row[i] -= L;
}

// ---------------- launch ----------------
extern "C" void kernel_launch(void* const* d_in, const int* in_sizes, int n_in,
                              void* d_out, int out_size)
{
    const float* x    = (const float*)d_in[0];
    const float* Wih  = (const float*)d_in[1];
    const float* Whh  = (const float*)d_in[2];
    const float* bih  = (const float*)d_in[3];
    const float* bhh  = (const float*)d_in[4];
    const float* Wd   = (const float*)d_in[5];
    const float* bd   = (const float*)d_in[6];
    float* out = (float*)d_out;

    const size_t smem_bytes = (size_t)3 * 8 * WPAD * sizeof(float);  // 98688
    cudaFuncSetAttribute(gru_mma, cudaFuncAttributeMaxDynamicSharedMemorySize,
                         (int)smem_bytes);

    init_kernel<<<64, 1024>>>();
    bhh_copy_kernel<<<(H3_ + 255) / 256, 256>>>(bhh);
    wfrag_kernel<<<1536, 256>>>(Whh);
    gi_kernel<<<dim3(48, T_), 256>>>(x, Wih, bih);
    gru_mma<<<NB, 256, smem_bytes>>>();
    dense_kernel<<<(OUT_ + 63) / 64, 256>>>(Wd, bd, out);
    lsm_kernel<<<B_, 256>>>(out);
}

// round 10
// speedup vs baseline: 2.1102x; 1.1168x over previous
#include <cuda_runtime.h>
#include <math.h>
#include <cstdint>

#define T_    512
#define B_    64
#define IN_   256
#define H_    1024
#define H3_   3072
#define OUT_  50257

#define NB    64          // persistent blocks; block owns 16 gate-columns
#define WPAD  1028        // padded word stride per warp-slice in reduction smem

// ---------------- device scratch ----------------
__device__ float g_gi[(size_t)T_ * B_ * H3_];    // [T][B][3H]
__device__ float g_hT0[H_ * B_];                 // h fp32 [col][b]
__device__ uint4 g_wfrag[64 * 3 * 64 * 32 * 2];  // W frags: [(blk*3+mt)*64+ktg][lane][hi|lo]
__device__ uint4 g_hfrag[2][8 * 64 * 32];        // h frags, double-buffered by step parity
__device__ float g_bhh[H3_];
__device__ unsigned g_sub[8 * 32];               // two-level barrier sub-counters (128B apart)
__device__ unsigned g_master;
__device__ unsigned g_bar_phase;

typedef unsigned long long u64;

#define FMA2(acc, a, b) asm("fma.rn.f32x2 %0, %1, %2, %0;" : "+l"(acc) : "l"(a), "l"(b))

static __device__ __forceinline__ float lo32(u64 v){ return __uint_as_float((unsigned)(v & 0xffffffffull)); }
static __device__ __forceinline__ float hi32(u64 v){ return __uint_as_float((unsigned)(v >> 32)); }
static __device__ __forceinline__ float sigmoidf_(float x){ return 1.0f / (1.0f + expf(-x)); }
static __device__ __forceinline__ float tanhf_(float x){
    float e = expf(-2.0f * fabsf(x));
    float t = (1.0f - e) / (1.0f + e);
    return copysignf(t, x);
}

// manual bf16 round-to-nearest-even
static __device__ __forceinline__ unsigned f2bf(float f){
    unsigned u = __float_as_uint(f);
    unsigned r = u + 0x7FFFu + ((u >> 16) & 1u);
    return (r >> 16) & 0xFFFFu;
}
static __device__ __forceinline__ float bf2f(unsigned s){
    return __uint_as_float(s << 16);
}
static __device__ __forceinline__ unsigned pack_bf2(float a, float b){
    return f2bf(a) | (f2bf(b) << 16);
}

// mma.sync bf16: D = A(16x16) * B(16x8) + D
#define MMA_BF16(C, A, b0v, b1v) \
    asm volatile("mma.sync.aligned.m16n8k16.row.col.f32.bf16.bf16.f32 " \
        "{%0,%1,%2,%3}, {%4,%5,%6,%7}, {%8,%9}, {%0,%1,%2,%3};" \
        : "+f"((C)[0]), "+f"((C)[1]), "+f"((C)[2]), "+f"((C)[3]) \
        : "r"((A).x), "r"((A).y), "r"((A).z), "r"((A).w), "r"(b0v), "r"(b1v))

// ---------------- init ----------------
__global__ void init_kernel(){
    int i = blockIdx.x * blockDim.x + threadIdx.x;
    if (i < H_ * B_) g_hT0[i] = 0.0f;
    if (i < 8 * 64 * 32){
        g_hfrag[0][i] = make_uint4(0u, 0u, 0u, 0u);
        g_hfrag[1][i] = make_uint4(0u, 0u, 0u, 0u);
    }
    if (i < 8 * 32) g_sub[i] = 0u;
    if (i == 0){ g_master = 0u; g_bar_phase = 0u; }
}

__global__ void bhh_copy_kernel(const float* __restrict__ bhh){
    int i = blockIdx.x * 256 + threadIdx.x;
    if (i < H3_) g_bhh[i] = bhh[i];
}

// ---------------- W_hh -> fragment layout (hi/lo bf16 planes) ----------------
__global__ void wfrag_kernel(const float* __restrict__ Whh){
    int gid = blockIdx.x * 256 + threadIdx.x;
    int lane = gid & 31;
    int tile = gid >> 5;
    if (tile >= 64 * 3 * 64) return;
    int ktg = tile & 63;
    int mt  = (tile >> 6) % 3;
    int blk = tile / 192;
    int c0  = blk * 16;
    int row0 = mt * H_ + c0;
    int j = lane >> 2;
    int k = ktg * 16 + (lane & 3) * 2;

    const float* W = Whh;
    float w00 = W[(size_t)(row0 + j    ) * H_ + k    ];
    float w01 = W[(size_t)(row0 + j    ) * H_ + k + 1];
    float w10 = W[(size_t)(row0 + j + 8) * H_ + k    ];
    float w11 = W[(size_t)(row0 + j + 8) * H_ + k + 1];
    float w02 = W[(size_t)(row0 + j    ) * H_ + k + 8];
    float w03 = W[(size_t)(row0 + j    ) * H_ + k + 9];
    float w12 = W[(size_t)(row0 + j + 8) * H_ + k + 8];
    float w13 = W[(size_t)(row0 + j + 8) * H_ + k + 9];

    uint4 hi, lo;
    hi.x = pack_bf2(w00, w01); hi.y = pack_bf2(w10, w11);
    hi.z = pack_bf2(w02, w03); hi.w = pack_bf2(w12, w13);
    lo.x = pack_bf2(w00 - bf2f(f2bf(w00)), w01 - bf2f(f2bf(w01)));
    lo.y = pack_bf2(w10 - bf2f(f2bf(w10)), w11 - bf2f(f2bf(w11)));
    lo.z = pack_bf2(w02 - bf2f(f2bf(w02)), w03 - bf2f(f2bf(w03)));
    lo.w = pack_bf2(w12 - bf2f(f2bf(w12)), w13 - bf2f(f2bf(w13)));

    g_wfrag[(size_t)tile * 64 + lane * 2    ] = hi;
    g_wfrag[(size_t)tile * 64 + lane * 2 + 1] = lo;
}

// ---------------- GI = in_seq @ W_ih^T + b_ih (passing form) ----------------
__global__ __launch_bounds__(256) void gi_kernel(const float* __restrict__ x,
                                                 const float* __restrict__ Wih,
                                                 const float* __restrict__ bih)
{
    __shared__ __align__(16) float  As[16][72];
    __shared__ __align__(16) float2 Bsd[16][66];

    const int tid = threadIdx.x;
    const int tx = tid & 15;
    const int ty = tid >> 4;
    const int lrow = tid >> 2;
    const int lkq = tid & 3;
    const int t  = blockIdx.y;
    const int j0 = blockIdx.x * 64;

    const float* arow = x   + (size_t)lrow * (T_ * IN_) + (size_t)t * IN_;
    const float* brow = Wih + (size_t)(j0 + lrow) * IN_;

    u64 acc[4][2];
    #pragma unroll
    for (int j = 0; j < 4; j++){ acc[j][0] = 0ull; acc[j][1] = 0ull; }

    for (int k0 = 0; k0 < IN_; k0 += 16){
        float4 av = *(const float4*)(arow + k0 + lkq * 4);
        float4 bv = *(const float4*)(brow + k0 + lkq * 4);
        As[lkq*4+0][lrow] = av.x; As[lkq*4+1][lrow] = av.y;
        As[lkq*4+2][lrow] = av.z; As[lkq*4+3][lrow] = av.w;
        Bsd[lkq*4+0][lrow] = make_float2(bv.x, bv.x);
        Bsd[lkq*4+1][lrow] = make_float2(bv.y, bv.y);
        Bsd[lkq*4+2][lrow] = make_float2(bv.z, bv.z);
        Bsd[lkq*4+3][lrow] = make_float2(bv.w, bv.w);
        __syncthreads();
        #pragma unroll
        for (int kk = 0; kk < 16; kk++){
            ulonglong2 a   = *(const ulonglong2*)&As[kk][ty * 4];
            ulonglong2 b01 = *(const ulonglong2*)&Bsd[kk][tx * 4];
            ulonglong2 b23 = *(const ulonglong2*)&Bsd[kk][tx * 4 + 2];
            FMA2(acc[0][0], a.x, b01.x); FMA2(acc[0][1], a.y, b01.x);
            FMA2(acc[1][0], a.x, b01.y); FMA2(acc[1][1], a.y, b01.y);
            FMA2(acc[2][0], a.x, b23.x); FMA2(acc[2][1], a.y, b23.x);
            FMA2(acc[3][0], a.x, b23.y); FMA2(acc[3][1], a.y, b23.y);
        }
        __syncthreads();
    }

    float4 bias = *(const float4*)(bih + j0 + tx * 4);
    #pragma unroll
    for (int p = 0; p < 2; p++){
        int m0 = ty * 4 + 2 * p;
        float4 v0;
        float4 v1;
        v0.x = lo32(acc[0][p]) + bias.x; v0.y = lo32(acc[1][p]) + bias.y;
        v0.z = lo32(acc[2][p]) + bias.z; v0.w = lo32(acc[3][p]) + bias.w;
        v1.x = hi32(acc[0][p]) + bias.x; v1.y = hi32(acc[1][p]) + bias.y;
        v1.z = hi32(acc[2][p]) + bias.z; v1.w = hi32(acc[3][p]) + bias.w;
        *(float4*)&g_gi[(size_t)(t * B_ + m0    ) * H3_ + j0 + tx * 4] = v0;
        *(float4*)&g_gi[(size_t)(t * B_ + m0 + 1) * H3_ + j0 + tx * 4] = v1;
    }
}

// ---------------- two-level grid barrier ----------------
static __device__ __forceinline__ void grid_bar(int tid, int blk, unsigned target){
    __threadfence();
    __syncthreads();
    if (tid == 0){
        unsigned a;
        unsigned* subp = &g_sub[(blk >> 3) * 32];
        asm volatile("atom.acq_rel.gpu.global.add.u32 %0, [%1], %2;"
                     : "=r"(a) : "l"(subp), "r"(1u) : "memory");
        bool released = false;
        if (a == 7u){
            unsigned m;
            asm volatile("atom.acq_rel.gpu.global.add.u32 %0, [%1], %2;"
                         : "=r"(m) : "l"(&g_master), "r"(1u) : "memory");
            if (m == 7u){
                #pragma unroll
                for (int i = 0; i < 8; i++) g_sub[i * 32] = 0u;
                g_master = 0u;
                __threadfence();
                asm volatile("st.release.gpu.global.u32 [%0], %1;"
                             :: "l"(&g_bar_phase), "r"(target) : "memory");
                released = true;
            }
        }
        if (!released){
            unsigned pcur;
            do {
                asm volatile("ld.acquire.gpu.global.u32 %0, [%1];"
                             : "=r"(pcur) : "l"(&g_bar_phase) : "memory");
            } while (pcur < target);
        }
    }
    __syncthreads();
}

// ---------------- persistent HMMA recurrence ----------------
__global__ __launch_bounds__(256, 1) void gru_mma()
{
    extern __shared__ float red[];   // [3 gates][8 warps][WPAD words]

    const int tid = threadIdx.x;
    const int w   = tid >> 5;        // warp id; MMA: k-slice owner; gates: nt owner
    const int l   = tid & 31;
    const int blk = blockIdx.x;
    const int c0  = blk * 16;

    // gate-phase ownership: (cols c0+jj, c0+jj+8) x (batches n0, n0+1)
    const int jj = l >> 2;                 // 0..7
    const int n0 = w * 8 + (l & 3) * 2;    // 0..62

    const float bhr0 = g_bhh[c0 + jj];
    const float bhr1 = g_bhh[c0 + jj + 8];
    const float bhz0 = g_bhh[H_ + c0 + jj];
    const float bhz1 = g_bhh[H_ + c0 + jj + 8];
    const float bhn0 = g_bhh[2 * H_ + c0 + jj];
    const float bhn1 = g_bhh[2 * H_ + c0 + jj + 8];

    const uint4* wf = g_wfrag;
    unsigned bar_t = 0;

    #pragma unroll 1
    for (int t = 0; t < T_; t++){
        const uint4* hfr = g_hfrag[t & 1];
        unsigned short* hfw = (unsigned short*)&g_hfrag[(t + 1) & 1][0];

        // prefetch gi + h_old (hidden under the MMA phase)
        // r-index decode: 0:(jj,n0) 1:(jj,n0+1) 2:(jj+8,n0) 3:(jj+8,n0+1)
        const float* gib = g_gi + (size_t)t * (B_ * H3_);
        float gir[4], giz[4], gin[4], hold[4];
        #pragma unroll
        for (int r = 0; r < 4; r++){
            int jsel = (r >> 1) ? (jj + 8) : jj;
            int nn   = n0 + (r & 1);
            const float* g = gib + (size_t)nn * H3_ + c0 + jsel;
            gir[r] = g[0]; giz[r] = g[H_]; gin[r] = g[2 * H_];
            hold[r] = g_hT0[(size_t)(c0 + jsel) * B_ + nn];
        }

        // ---- MMA phase: C[3 gates][8 n-tiles][4] over this warp's k-slice ----
        float C[3][8][4];
        #pragma unroll
        for (int mt = 0; mt < 3; mt++)
            #pragma unroll
            for (int nt = 0; nt < 8; nt++)
                #pragma unroll
                for (int r = 0; r < 4; r++) C[mt][nt][r] = 0.0f;

        #pragma unroll 1
        for (int kt8 = 0; kt8 < 8; kt8++){
            const int ktg = kt8 * 8 + w;
            uint4 Ah[3], Al[3];
            #pragma unroll
            for (int mt = 0; mt < 3; mt++){
                size_t ti = ((size_t)(blk * 3 + mt) * 64 + ktg) * 64 + l * 2;
                Ah[mt] = wf[ti];
                Al[mt] = wf[ti + 1];
            }
            uint4 Bv[8];
            #pragma unroll
            for (int nt = 0; nt < 8; nt++)
                Bv[nt] = __ldcg(&hfr[(size_t)(nt * 64 + ktg) * 32 + l]);

            #pragma unroll
            for (int mt = 0; mt < 3; mt++){
                #pragma unroll
                for (int nt = 0; nt < 8; nt++){
                    MMA_BF16(C[mt][nt], Ah[mt], Bv[nt].x, Bv[nt].y);  // Wh*Hh
                    MMA_BF16(C[mt][nt], Ah[mt], Bv[nt].z, Bv[nt].w);  // Wh*Hl
                    MMA_BF16(C[mt][nt], Al[mt], Bv[nt].x, Bv[nt].y);  // Wl*Hh
                }
            }
        }

        // ---- store partials to padded smem (conflict-free STS.128) ----
        #pragma unroll
        for (int mt = 0; mt < 3; mt++){
            #pragma unroll
            for (int nt = 0; nt < 8; nt++){
                int wordu = (mt * 8 + w) * WPAD + (nt * 32 + l) * 4;
                *(float4*)&red[wordu] = make_float4(C[mt][nt][0], C[mt][nt][1],
                                                    C[mt][nt][2], C[mt][nt][3]);
            }
        }
        __syncthreads();

        // ---- conflict-free cross-warp reduce (LDS.128, lane-contiguous) ----
        float gh[3][4];
        #pragma unroll
        for (int g = 0; g < 3; g++){
            float4 s = make_float4(0.f, 0.f, 0.f, 0.f);
            #pragma unroll
            for (int wv = 0; wv < 8; wv++){
                float4 v = *(const float4*)&red[(g * 8 + wv) * WPAD + (w * 32 + l) * 4];
                s.x += v.x; s.y += v.y; s.z += v.z; s.w += v.w;
            }
            gh[g][0] = s.x; gh[g][1] = s.y; gh[g][2] = s.z; gh[g][3] = s.w;
        }
        __syncthreads();

        // ---- fused gates + h update ----
        float hnew[4];
        #pragma unroll
        for (int r = 0; r < 4; r++){
            float bR = (r >> 1) ? bhr1 : bhr0;
            float bZ = (r >> 1) ? bhz1 : bhz0;
            float bN = (r >> 1) ? bhn1 : bhn0;
            float rg = sigmoidf_(gir[r] + gh[0][r] + bR);
            float zg = sigmoidf_(giz[r] + gh[1][r] + bZ);
            float ng = tanhf_(gin[r] + rg * (gh[2][r] + bN));
            hnew[r] = (1.0f - zg) * ng + zg * hold[r];
        }

        // fp32 master
        *(float2*)&g_hT0[(size_t)(c0 + jj    ) * B_ + n0] = make_float2(hnew[0], hnew[1]);
        *(float2*)&g_hT0[(size_t)(c0 + jj + 8) * B_ + n0] = make_float2(hnew[2], hnew[3]);

        // bf16 hi/lo fragment planes -> NEXT step's buffer
        #pragma unroll
        for (int p = 0; p < 2; p++){
            int lb = ((n0 + p) & 7) * 4 + (jj >> 1);
            size_t base16 = (((size_t)w * 64 + blk) * 32 + lb) * 8;
            unsigned h0 = f2bf(hnew[p]);
            hfw[base16 + 0 + (jj & 1)] = (unsigned short)h0;                       // hi b0
            hfw[base16 + 4 + (jj & 1)] = (unsigned short)f2bf(hnew[p] - bf2f(h0)); // lo b0
            unsigned h1 = f2bf(hnew[2 + p]);
            hfw[base16 + 2 + (jj & 1)] = (unsigned short)h1;                           // hi b1
            hfw[base16 + 6 + (jj & 1)] = (unsigned short)f2bf(hnew[2 + p] - bf2f(h1)); // lo b1
        }

        bar_t += 1u;
        grid_bar(tid, blk, bar_t);
    }
}

// ---------------- logits = h_final @ W_dense^T + b_dense ----------------
__global__ __launch_bounds__(256) void dense_kernel(const float* __restrict__ Wd,
                                                    const float* __restrict__ bd,
                                                    float* __restrict__ out)
{
    __shared__ __align__(16) float  As[16][72];
    __shared__ __align__(16) float2 Bsd[16][66];

    const int tid = threadIdx.x;
    const int tx = tid & 15;
    const int ty = tid >> 4;
    const int lrow = tid >> 2;
    const int lkq = tid & 3;
    const int kk_ld = tid >> 4;
    const int bq_ld = (tid & 15) * 4;
    const int j0 = blockIdx.x * 64;

    const int jrow = j0 + lrow;
    const bool jok = (jrow < OUT_);
    const float* brow = Wd + (size_t)(jok ? jrow : 0) * H_;

    u64 acc[4][2];
    #pragma unroll
    for (int j = 0; j < 4; j++){ acc[j][0] = 0ull; acc[j][1] = 0ull; }

    for (int k0 = 0; k0 < H_; k0 += 16){
        float4 av = *(const float4*)(g_hT0 + (size_t)(k0 + kk_ld) * B_ + bq_ld);
        float4 bv = make_float4(0.f, 0.f, 0.f, 0.f);
        if (jok) bv = *(const float4*)(brow + k0 + lkq * 4);
        *(float4*)&As[kk_ld][bq_ld] = av;
        Bsd[lkq*4+0][lrow] = make_float2(bv.x, bv.x);
        Bsd[lkq*4+1][lrow] = make_float2(bv.y, bv.y);
        Bsd[lkq*4+2][lrow] = make_float2(bv.z, bv.z);
        Bsd[lkq*4+3][lrow] = make_float2(bv.w, bv.w);
        __syncthreads();
        #pragma unroll
        for (int kk = 0; kk < 16; kk++){
            ulonglong2 a   = *(const ulonglong2*)&As[kk][ty * 4];
            ulonglong2 b01 = *(const ulonglong2*)&Bsd[kk][tx * 4];
            ulonglong2 b23 = *(const ulonglong2*)&Bsd[kk][tx * 4 + 2];
            FMA2(acc[0][0], a.x, b01.x); FMA2(acc[0][1], a.y, b01.x);
            FMA2(acc[1][0], a.x, b01.y); FMA2(acc[1][1], a.y, b01.y);
            FMA2(acc[2][0], a.x, b23.x); FMA2(acc[2][1], a.y, b23.x);
            FMA2(acc[3][0], a.x, b23.y); FMA2(acc[3][1], a.y, b23.y);
        }
        __syncthreads();
    }

    #pragma unroll
    for (int p = 0; p < 2; p++){
        #pragma unroll
        for (int half = 0; half < 2; half++){
            int m = ty * 4 + 2 * p + half;
            #pragma unroll
            for (int jj = 0; jj < 4; jj++){
                int col = j0 + tx * 4 + jj;
                if (col < OUT_){
                    float v = half ? hi32(acc[jj][p]) : lo32(acc[jj][p]);
                    out[(size_t)m * OUT_ + col] = v + bd[col];
                }
            }
        }
    }
}

// ---------------- in-place row-wise log_softmax ----------------
__global__ __launch_bounds__(256) void lsm_kernel(float* __restrict__ out)
{
    __shared__ float red[256];
    const int tid = threadIdx.x;
    float* row = out + (size_t)blockIdx.x * OUT_;

    float m = -1e30f;
    for (int i = tid; i < OUT_; i += 256) m = fmaxf(m, row[i]);
    red[tid] = m; __syncthreads();
    for (int s = 128; s > 0; s >>= 1){
        if (tid < s) red[tid] = fmaxf(red[tid], red[tid + s]);
        __syncthreads();
    }
    float M = red[0];
    __syncthreads();

    float sm = 0.0f;
    for (int i = tid; i < OUT_; i += 256) sm += expf(row[i] - M);
    red[tid] = sm; __syncthreads();
    for (int s = 128; s > 0; s >>= 1){
        if (tid < s) red[tid] += red[tid + s];
        __syncthreads();
    }
    float L = M + logf(red[0]);
    for (int i = tid; i < OUT_; i += 256) row[i] -= L;
}

// ---------------- launch ----------------
extern "C" void kernel_launch(void* const* d_in, const int* in_sizes, int n_in,
                              void* d_out, int out_size)
{
    const float* x    = (const float*)d_in[0];
    const float* Wih  = (const float*)d_in[1];
    const float* Whh  = (const float*)d_in[2];
    const float* bih  = (const float*)d_in[3];
    const float* bhh  = (const float*)d_in[4];
    const float* Wd   = (const float*)d_in[5];
    const float* bd   = (const float*)d_in[6];
    float* out = (float*)d_out;

    const size_t smem_bytes = (size_t)3 * 8 * WPAD * sizeof(float);  // 98688
    cudaFuncSetAttribute(gru_mma, cudaFuncAttributeMaxDynamicSharedMemorySize,
                         (int)smem_bytes);

    init_kernel<<<64, 1024>>>();
    bhh_copy_kernel<<<(H3_ + 255) / 256, 256>>>(bhh);
    wfrag_kernel<<<1536, 256>>>(Whh);
    gi_kernel<<<dim3(48, T_), 256>>>(x, Wih, bih);
    gru_mma<<<NB, 256, smem_bytes>>>();
    dense_kernel<<<(OUT_ + 63) / 64, 256>>>(Wd, bd, out);
    lsm_kernel<<<B_, 256>>>(out);
}

// round 11
// speedup vs baseline: 2.5247x; 1.1964x over previous
#include <cuda_runtime.h>
#include <math.h>
#include <cstdint>

#define T_    512
#define B_    64
#define IN_   256
#define H_    1024
#define H3_   3072
#define OUT_  50257

#define NB    128         // persistent blocks; block = 16 cols x 32 batches
#define WPAD  516         // padded word stride per (gate,warp) slice: 4*32*4=512 + 4

// ---------------- device scratch ----------------
__device__ float g_gi[(size_t)T_ * B_ * H3_];    // [T][B][3H]
__device__ float g_hT0[H_ * B_];                 // h fp32 [col][b] (written at final step)
__device__ uint4 g_wfrag[64 * 3 * 64 * 32 * 2];  // W frags: [(cg*3+mt)*64+ktg][lane][hi|lo]
__device__ uint4 g_hfrag[2][8 * 64 * 32];        // h frags, double-buffered by step parity
__device__ float g_bhh[H3_];
__device__ unsigned g_sub[16 * 32];              // two-level barrier sub-counters
__device__ unsigned g_master;
__device__ unsigned g_bar_phase;

typedef unsigned long long u64;

#define FMA2(acc, a, b) asm("fma.rn.f32x2 %0, %1, %2, %0;" : "+l"(acc) : "l"(a), "l"(b))

static __device__ __forceinline__ float lo32(u64 v){ return __uint_as_float((unsigned)(v & 0xffffffffull)); }
static __device__ __forceinline__ float hi32(u64 v){ return __uint_as_float((unsigned)(v >> 32)); }
static __device__ __forceinline__ float sigmoidf_(float x){ return 1.0f / (1.0f + expf(-x)); }
static __device__ __forceinline__ float tanhf_(float x){
    float e = expf(-2.0f * fabsf(x));
    float t = (1.0f - e) / (1.0f + e);
    return copysignf(t, x);
}

// manual bf16 round-to-nearest-even
static __device__ __forceinline__ unsigned f2bf(float f){
    unsigned u = __float_as_uint(f);
    unsigned r = u + 0x7FFFu + ((u >> 16) & 1u);
    return (r >> 16) & 0xFFFFu;
}
static __device__ __forceinline__ float bf2f(unsigned s){
    return __uint_as_float(s << 16);
}
static __device__ __forceinline__ unsigned pack_bf2(float a, float b){
    return f2bf(a) | (f2bf(b) << 16);
}

// mma.sync bf16: D = A(16x16) * B(16x8) + D
#define MMA_BF16(C, A, b0v, b1v) \
    asm volatile("mma.sync.aligned.m16n8k16.row.col.f32.bf16.bf16.f32 " \
        "{%0,%1,%2,%3}, {%4,%5,%6,%7}, {%8,%9}, {%0,%1,%2,%3};" \
        : "+f"((C)[0]), "+f"((C)[1]), "+f"((C)[2]), "+f"((C)[3]) \
        : "r"((A).x), "r"((A).y), "r"((A).z), "r"((A).w), "r"(b0v), "r"(b1v))

// ---------------- init ----------------
__global__ void init_kernel(){
    int i = blockIdx.x * blockDim.x + threadIdx.x;
    if (i < H_ * B_) g_hT0[i] = 0.0f;
    if (i < 8 * 64 * 32){
        g_hfrag[0][i] = make_uint4(0u, 0u, 0u, 0u);
        g_hfrag[1][i] = make_uint4(0u, 0u, 0u, 0u);
    }
    if (i < 16 * 32) g_sub[i] = 0u;
    if (i == 0){ g_master = 0u; g_bar_phase = 0u; }
}

__global__ void bhh_copy_kernel(const float* __restrict__ bhh){
    int i = blockIdx.x * 256 + threadIdx.x;
    if (i < H3_) g_bhh[i] = bhh[i];
}

// ---------------- W_hh -> fragment layout (hi/lo bf16 planes) ----------------
__global__ void wfrag_kernel(const float* __restrict__ Whh){
    int gid = blockIdx.x * 256 + threadIdx.x;
    int lane = gid & 31;
    int tile = gid >> 5;
    if (tile >= 64 * 3 * 64) return;
    int ktg = tile & 63;
    int mt  = (tile >> 6) % 3;
    int cg  = tile / 192;
    int c0  = cg * 16;
    int row0 = mt * H_ + c0;
    int j = lane >> 2;
    int k = ktg * 16 + (lane & 3) * 2;

    const float* W = Whh;
    float w00 = W[(size_t)(row0 + j    ) * H_ + k    ];
    float w01 = W[(size_t)(row0 + j    ) * H_ + k + 1];
    float w10 = W[(size_t)(row0 + j + 8) * H_ + k    ];
    float w11 = W[(size_t)(row0 + j + 8) * H_ + k + 1];
    float w02 = W[(size_t)(row0 + j    ) * H_ + k + 8];
    float w03 = W[(size_t)(row0 + j    ) * H_ + k + 9];
    float w12 = W[(size_t)(row0 + j + 8) * H_ + k + 8];
    float w13 = W[(size_t)(row0 + j + 8) * H_ + k + 9];

    uint4 hi, lo;
    hi.x = pack_bf2(w00, w01); hi.y = pack_bf2(w10, w11);
    hi.z = pack_bf2(w02, w03); hi.w = pack_bf2(w12, w13);
    lo.x = pack_bf2(w00 - bf2f(f2bf(w00)), w01 - bf2f(f2bf(w01)));
    lo.y = pack_bf2(w10 - bf2f(f2bf(w10)), w11 - bf2f(f2bf(w11)));
    lo.z = pack_bf2(w02 - bf2f(f2bf(w02)), w03 - bf2f(f2bf(w03)));
    lo.w = pack_bf2(w12 - bf2f(f2bf(w12)), w13 - bf2f(f2bf(w13)));

    g_wfrag[(size_t)tile * 64 + lane * 2    ] = hi;
    g_wfrag[(size_t)tile * 64 + lane * 2 + 1] = lo;
}

// ---------------- GI = in_seq @ W_ih^T + b_ih (passing form) ----------------
__global__ __launch_bounds__(256) void gi_kernel(const float* __restrict__ x,
                                                 const float* __restrict__ Wih,
                                                 const float* __restrict__ bih)
{
    __shared__ __align__(16) float  As[16][72];
    __shared__ __align__(16) float2 Bsd[16][66];

    const int tid = threadIdx.x;
    const int tx = tid & 15;
    const int ty = tid >> 4;
    const int lrow = tid >> 2;
    const int lkq = tid & 3;
    const int t  = blockIdx.y;
    const int j0 = blockIdx.x * 64;

    const float* arow = x   + (size_t)lrow * (T_ * IN_) + (size_t)t * IN_;
    const float* brow = Wih + (size_t)(j0 + lrow) * IN_;

    u64 acc[4][2];
    #pragma unroll
    for (int j = 0; j < 4; j++){ acc[j][0] = 0ull; acc[j][1] = 0ull; }

    for (int k0 = 0; k0 < IN_; k0 += 16){
        float4 av = *(const float4*)(arow + k0 + lkq * 4);
        float4 bv = *(const float4*)(brow + k0 + lkq * 4);
        As[lkq*4+0][lrow] = av.x; As[lkq*4+1][lrow] = av.y;
        As[lkq*4+2][lrow] = av.z; As[lkq*4+3][lrow] = av.w;
        Bsd[lkq*4+0][lrow] = make_float2(bv.x, bv.x);
        Bsd[lkq*4+1][lrow] = make_float2(bv.y, bv.y);
        Bsd[lkq*4+2][lrow] = make_float2(bv.z, bv.z);
        Bsd[lkq*4+3][lrow] = make_float2(bv.w, bv.w);
        __syncthreads();
        #pragma unroll
        for (int kk = 0; kk < 16; kk++){
            ulonglong2 a   = *(const ulonglong2*)&As[kk][ty * 4];
            ulonglong2 b01 = *(const ulonglong2*)&Bsd[kk][tx * 4];
            ulonglong2 b23 = *(const ulonglong2*)&Bsd[kk][tx * 4 + 2];
            FMA2(acc[0][0], a.x, b01.x); FMA2(acc[0][1], a.y, b01.x);
            FMA2(acc[1][0], a.x, b01.y); FMA2(acc[1][1], a.y, b01.y);
            FMA2(acc[2][0], a.x, b23.x); FMA2(acc[2][1], a.y, b23.x);
            FMA2(acc[3][0], a.x, b23.y); FMA2(acc[3][1], a.y, b23.y);
        }
        __syncthreads();
    }

    float4 bias = *(const float4*)(bih + j0 + tx * 4);
    #pragma unroll
    for (int p = 0; p < 2; p++){
        int m0 = ty * 4 + 2 * p;
        float4 v0;
        float4 v1;
        v0.x = lo32(acc[0][p]) + bias.x; v0.y = lo32(acc[1][p]) + bias.y;
        v0.z = lo32(acc[2][p]) + bias.z; v0.w = lo32(acc[3][p]) + bias.w;
        v1.x = hi32(acc[0][p]) + bias.x; v1.y = hi32(acc[1][p]) + bias.y;
        v1.z = hi32(acc[2][p]) + bias.z; v1.w = hi32(acc[3][p]) + bias.w;
        *(float4*)&g_gi[(size_t)(t * B_ + m0    ) * H3_ + j0 + tx * 4] = v0;
        *(float4*)&g_gi[(size_t)(t * B_ + m0 + 1) * H3_ + j0 + tx * 4] = v1;
    }
}

// ---------------- two-level grid barrier (16 groups x 8) ----------------
static __device__ __forceinline__ void grid_bar(int tid, int blk, unsigned target){
    __threadfence();
    __syncthreads();
    if (tid == 0){
        unsigned a;
        unsigned* subp = &g_sub[(blk >> 3) * 32];
        asm volatile("atom.acq_rel.gpu.global.add.u32 %0, [%1], %2;"
                     : "=r"(a) : "l"(subp), "r"(1u) : "memory");
        bool released = false;
        if (a == 7u){
            unsigned m;
            asm volatile("atom.acq_rel.gpu.global.add.u32 %0, [%1], %2;"
                         : "=r"(m) : "l"(&g_master), "r"(1u) : "memory");
            if (m == 15u){
                #pragma unroll
                for (int i = 0; i < 16; i++) g_sub[i * 32] = 0u;
                g_master = 0u;
                __threadfence();
                asm volatile("st.release.gpu.global.u32 [%0], %1;"
                             :: "l"(&g_bar_phase), "r"(target) : "memory");
                released = true;
            }
        }
        if (!released){
            unsigned pcur;
            do {
                asm volatile("ld.acquire.gpu.global.u32 %0, [%1];"
                             : "=r"(pcur) : "l"(&g_bar_phase) : "memory");
            } while (pcur < target);
        }
    }
    __syncthreads();
}

// ---------------- persistent HMMA recurrence (128 blocks) ----------------
__global__ __launch_bounds__(256, 1) void gru_mma()
{
    extern __shared__ float red[];   // [3 gates][8 warps][WPAD words]

    const int tid = threadIdx.x;
    const int w   = tid >> 5;
    const int l   = tid & 31;
    const int blk = blockIdx.x;
    const int cg  = blk >> 1;          // column group (W rows / h-frag k-tile)
    const int c0  = cg * 16;
    const int nb0 = (blk & 1) * 32;    // batch base
    const int ntb = (blk & 1) * 4;     // global batch-tile base

    // gate-phase decode: thread -> (batch tile gntl, col jj/jj+8, batch-in-tile gnc)
    const int gntl = tid >> 6;           // 0..3
    const int grem = tid & 63;
    const int gjj  = grem >> 3;          // 0..7
    const int gnc  = grem & 7;           // 0..7
    const int gn   = nb0 + gntl * 8 + gnc;
    const int lane_r = gjj * 4 + (gnc >> 1);
    const int rp   = gnc & 1;

    const float bhr0 = g_bhh[c0 + gjj];
    const float bhr1 = g_bhh[c0 + gjj + 8];
    const float bhz0 = g_bhh[H_ + c0 + gjj];
    const float bhz1 = g_bhh[H_ + c0 + gjj + 8];
    const float bhn0 = g_bhh[2 * H_ + c0 + gjj];
    const float bhn1 = g_bhh[2 * H_ + c0 + gjj + 8];

    float hold0 = 0.0f;   // h for (c0+gjj, gn), persistent in registers
    float hold1 = 0.0f;   // h for (c0+gjj+8, gn)

    const uint4* wf = g_wfrag;
    unsigned bar_t = 0;

    #pragma unroll 1
    for (int t = 0; t < T_; t++){
        const uint4* hfr = g_hfrag[t & 1];
        unsigned short* hfw = (unsigned short*)&g_hfrag[(t + 1) & 1][0];

        // prefetch gi for the gate phase (consumed after the MMA phase)
        const float* gA = g_gi + ((size_t)t * B_ + gn) * H3_ + c0 + gjj;
        float gir0 = gA[0],      gir1 = gA[8];
        float giz0 = gA[H_],     giz1 = gA[H_ + 8];
        float gin0 = gA[2 * H_], gin1 = gA[2 * H_ + 8];

        // ---- MMA phase: warp owns k-slice [w*8, w*8+8), all 3 mt x 4 nt ----
        float C[3][4][4];
        #pragma unroll
        for (int mt = 0; mt < 3; mt++)
            #pragma unroll
            for (int nt = 0; nt < 4; nt++)
                #pragma unroll
                for (int r = 0; r < 4; r++) C[mt][nt][r] = 0.0f;

        #pragma unroll 2
        for (int kt = 0; kt < 8; kt++){
            const int ktg = w * 8 + kt;
            uint4 Ah[3], Al[3];
            #pragma unroll
            for (int mt = 0; mt < 3; mt++){
                size_t ti = ((size_t)(cg * 3 + mt) * 64 + ktg) * 64 + l * 2;
                Ah[mt] = wf[ti];
                Al[mt] = wf[ti + 1];
            }
            uint4 Bv[4];
            #pragma unroll
            for (int nt = 0; nt < 4; nt++)
                Bv[nt] = __ldcg(&hfr[(size_t)((ntb + nt) * 64 + ktg) * 32 + l]);

            #pragma unroll
            for (int mt = 0; mt < 3; mt++){
                #pragma unroll
                for (int nt = 0; nt < 4; nt++){
                    MMA_BF16(C[mt][nt], Ah[mt], Bv[nt].x, Bv[nt].y);  // Wh*Hh
                    MMA_BF16(C[mt][nt], Ah[mt], Bv[nt].z, Bv[nt].w);  // Wh*Hl
                    MMA_BF16(C[mt][nt], Al[mt], Bv[nt].x, Bv[nt].y);  // Wl*Hh
                }
            }
        }

        // ---- store partials (conflict-free STS.128) ----
        #pragma unroll
        for (int mt = 0; mt < 3; mt++){
            #pragma unroll
            for (int nt = 0; nt < 4; nt++){
                int wordu = (mt * 8 + w) * WPAD + (nt * 32 + l) * 4;
                *(float4*)&red[wordu] = make_float4(C[mt][nt][0], C[mt][nt][1],
                                                    C[mt][nt][2], C[mt][nt][3]);
            }
        }
        __syncthreads();

        // ---- cross-warp reduce (8 partials) + gates ----
        float gh0[3], gh1[3];
        #pragma unroll
        for (int g = 0; g < 3; g++){
            float4 s = make_float4(0.f, 0.f, 0.f, 0.f);
            #pragma unroll
            for (int wv = 0; wv < 8; wv++){
                float4 v = *(const float4*)&red[(g * 8 + wv) * WPAD + (gntl * 32 + lane_r) * 4];
                s.x += v.x; s.y += v.y; s.z += v.z; s.w += v.w;
            }
            gh0[g] = rp ? s.y : s.x;   // reg rp     -> (gjj,   gn)
            gh1[g] = rp ? s.w : s.z;   // reg 2+rp   -> (gjj+8, gn)
        }

        float r0 = sigmoidf_(gir0 + gh0[0] + bhr0);
        float z0 = sigmoidf_(giz0 + gh0[1] + bhz0);
        float n0 = tanhf_(gin0 + r0 * (gh0[2] + bhn0));
        float hn0 = (1.0f - z0) * n0 + z0 * hold0;
        hold0 = hn0;

        float r1 = sigmoidf_(gir1 + gh1[0] + bhr1);
        float z1 = sigmoidf_(giz1 + gh1[1] + bhz1);
        float n1 = tanhf_(gin1 + r1 * (gh1[2] + bhn1));
        float hn1 = (1.0f - z1) * n1 + z1 * hold1;
        hold1 = hn1;

        // ---- write bf16 hi/lo fragment planes -> NEXT step's buffer ----
        {
            int lb = gnc * 4 + (gjj >> 1);
            size_t base16 = (((size_t)(ntb + gntl) * 64 + cg) * 32 + lb) * 8;
            unsigned h0 = f2bf(hn0);
            hfw[base16 + 0 + (gjj & 1)] = (unsigned short)h0;                       // hi b0 (jj)
            hfw[base16 + 4 + (gjj & 1)] = (unsigned short)f2bf(hn0 - bf2f(h0));     // lo b0
            unsigned h1 = f2bf(hn1);
            hfw[base16 + 2 + (gjj & 1)] = (unsigned short)h1;                       // hi b1 (jj+8)
            hfw[base16 + 6 + (gjj & 1)] = (unsigned short)f2bf(hn1 - bf2f(h1));     // lo b1
        }

        if (t == T_ - 1){
            g_hT0[(size_t)(c0 + gjj    ) * B_ + gn] = hn0;
            g_hT0[(size_t)(c0 + gjj + 8) * B_ + gn] = hn1;
        }

        bar_t += 1u;
        grid_bar(tid, blk, bar_t);
    }
}

// ---------------- logits = h_final @ W_dense^T + b_dense ----------------
__global__ __launch_bounds__(256) void dense_kernel(const float* __restrict__ Wd,
                                                    const float* __restrict__ bd,
                                                    float* __restrict__ out)
{
    __shared__ __align__(16) float  As[16][72];
    __shared__ __align__(16) float2 Bsd[16][66];

    const int tid = threadIdx.x;
    const int tx = tid & 15;
    const int ty = tid >> 4;
    const int lrow = tid >> 2;
    const int lkq = tid & 3;
    const int kk_ld = tid >> 4;
    const int bq_ld = (tid & 15) * 4;
    const int j0 = blockIdx.x * 64;

    const int jrow = j0 + lrow;
    const bool jok = (jrow < OUT_);
    const float* brow = Wd + (size_t)(jok ? jrow : 0) * H_;

    u64 acc[4][2];
    #pragma unroll
    for (int j = 0; j < 4; j++){ acc[j][0] = 0ull; acc[j][1] = 0ull; }

    for (int k0 = 0; k0 < H_; k0 += 16){
        float4 av = *(const float4*)(g_hT0 + (size_t)(k0 + kk_ld) * B_ + bq_ld);
        float4 bv = make_float4(0.f, 0.f, 0.f, 0.f);
        if (jok) bv = *(const float4*)(brow + k0 + lkq * 4);
        *(float4*)&As[kk_ld][bq_ld] = av;
        Bsd[lkq*4+0][lrow] = make_float2(bv.x, bv.x);
        Bsd[lkq*4+1][lrow] = make_float2(bv.y, bv.y);
        Bsd[lkq*4+2][lrow] = make_float2(bv.z, bv.z);
        Bsd[lkq*4+3][lrow] = make_float2(bv.w, bv.w);
        __syncthreads();
        #pragma unroll
        for (int kk = 0; kk < 16; kk++){
            ulonglong2 a   = *(const ulonglong2*)&As[kk][ty * 4];
            ulonglong2 b01 = *(const ulonglong2*)&Bsd[kk][tx * 4];
            ulonglong2 b23 = *(const ulonglong2*)&Bsd[kk][tx * 4 + 2];
            FMA2(acc[0][0], a.x, b01.x); FMA2(acc[0][1], a.y, b01.x);
            FMA2(acc[1][0], a.x, b01.y); FMA2(acc[1][1], a.y, b01.y);
            FMA2(acc[2][0], a.x, b23.x); FMA2(acc[2][1], a.y, b23.x);
            FMA2(acc[3][0], a.x, b23.y); FMA2(acc[3][1], a.y, b23.y);
        }
        __syncthreads();
    }

    #pragma unroll
    for (int p = 0; p < 2; p++){
        #pragma unroll
        for (int half = 0; half < 2; half++){
            int m = ty * 4 + 2 * p + half;
            #pragma unroll
            for (int jj = 0; jj < 4; jj++){
                int col = j0 + tx * 4 + jj;
                if (col < OUT_){
                    float v = half ? hi32(acc[jj][p]) : lo32(acc[jj][p]);
                    out[(size_t)m * OUT_ + col] = v + bd[col];
                }
            }
        }
    }
}

// ---------------- in-place row-wise log_softmax ----------------
__global__ __launch_bounds__(256) void lsm_kernel(float* __restrict__ out)
{
    __shared__ float red[256];
    const int tid = threadIdx.x;
    float* row = out + (size_t)blockIdx.x * OUT_;

    float m = -1e30f;
    for (int i = tid; i < OUT_; i += 256) m = fmaxf(m, row[i]);
    red[tid] = m; __syncthreads();
    for (int s = 128; s > 0; s >>= 1){
        if (tid < s) red[tid] = fmaxf(red[tid], red[tid + s]);
        __syncthreads();
    }
    float M = red[0];
    __syncthreads();

    float sm = 0.0f;
    for (int i = tid; i < OUT_; i += 256) sm += expf(row[i] - M);
    red[tid] = sm; __syncthreads();
    for (int s = 128; s > 0; s >>= 1){
        if (tid < s) red[tid] += red[tid + s];
        __syncthreads();
    }
    float L = M + logf(red[0]);
    for (int i = tid; i < OUT_; i += 256) row[i] -= L;
}

// ---------------- launch ----------------
extern "C" void kernel_launch(void* const* d_in, const int* in_sizes, int n_in,
                              void* d_out, int out_size)
{
    const float* x    = (const float*)d_in[0];
    const float* Wih  = (const float*)d_in[1];
    const float* Whh  = (const float*)d_in[2];
    const float* bih  = (const float*)d_in[3];
    const float* bhh  = (const float*)d_in[4];
    const float* Wd   = (const float*)d_in[5];
    const float* bd   = (const float*)d_in[6];
    float* out = (float*)d_out;

    const size_t smem_bytes = (size_t)3 * 8 * WPAD * sizeof(float);  // 49536
    cudaFuncSetAttribute(gru_mma, cudaFuncAttributeMaxDynamicSharedMemorySize,
                         (int)smem_bytes);

    init_kernel<<<64, 1024>>>();
    bhh_copy_kernel<<<(H3_ + 255) / 256, 256>>>(bhh);
    wfrag_kernel<<<1536, 256>>>(Whh);
    gi_kernel<<<dim3(48, T_), 256>>>(x, Wih, bih);
    gru_mma<<<NB, 256, smem_bytes>>>();
    dense_kernel<<<(OUT_ + 63) / 64, 256>>>(Wd, bd, out);
    lsm_kernel<<<B_, 256>>>(out);
}

// round 12
// speedup vs baseline: 2.5758x; 1.0202x over previous
#include <cuda_runtime.h>
#include <math.h>
#include <cstdint>

#define T_    512
#define B_    64
#define IN_   256
#define H_    1024
#define H3_   3072
#define OUT_  50257

#define NB    128         // persistent blocks; block = 16 cols x 32 batches
#define WPAD  516         // padded word stride per (gate,warp) slice

// ---------------- device scratch ----------------
__device__ float g_gi[(size_t)T_ * B_ * H3_];    // [T][B][3H]
__device__ float g_hT0[H_ * B_];                 // h fp32 [col][b] (written at final step)
__device__ uint4 g_wfrag[64 * 3 * 64 * 32 * 2];  // W frags: [(cg*3+mt)*64+ktg][lane][hi|lo]
__device__ uint4 g_hfrag[2][8 * 64 * 32];        // h frags, double-buffered by step parity
__device__ float g_bhh[H3_];
__device__ unsigned g_sub2[2][8 * 32];           // per-half sub-counters (monotonic)
__device__ unsigned g_master2[2 * 32];           // per-half master (monotonic)
__device__ unsigned g_phase2[2 * 32];            // per-half release phase

typedef unsigned long long u64;

#define FMA2(acc, a, b) asm("fma.rn.f32x2 %0, %1, %2, %0;" : "+l"(acc) : "l"(a), "l"(b))

static __device__ __forceinline__ float lo32(u64 v){ return __uint_as_float((unsigned)(v & 0xffffffffull)); }
static __device__ __forceinline__ float hi32(u64 v){ return __uint_as_float((unsigned)(v >> 32)); }
static __device__ __forceinline__ float sigmoidf_(float x){ return 1.0f / (1.0f + expf(-x)); }
static __device__ __forceinline__ float tanhf_(float x){
    float e = expf(-2.0f * fabsf(x));
    float t = (1.0f - e) / (1.0f + e);
    return copysignf(t, x);
}

// manual bf16 round-to-nearest-even
static __device__ __forceinline__ unsigned f2bf(float f){
    unsigned u = __float_as_uint(f);
    unsigned r = u + 0x7FFFu + ((u >> 16) & 1u);
    return (r >> 16) & 0xFFFFu;
}
static __device__ __forceinline__ float bf2f(unsigned s){
    return __uint_as_float(s << 16);
}
static __device__ __forceinline__ unsigned pack_bf2(float a, float b){
    return f2bf(a) | (f2bf(b) << 16);
}

// mma.sync bf16: D = A(16x16) * B(16x8) + D
#define MMA_BF16(C, A, b0v, b1v) \
    asm volatile("mma.sync.aligned.m16n8k16.row.col.f32.bf16.bf16.f32 " \
        "{%0,%1,%2,%3}, {%4,%5,%6,%7}, {%8,%9}, {%0,%1,%2,%3};" \
        : "+f"((C)[0]), "+f"((C)[1]), "+f"((C)[2]), "+f"((C)[3]) \
        : "r"((A).x), "r"((A).y), "r"((A).z), "r"((A).w), "r"(b0v), "r"(b1v))

// ---------------- init ----------------
__global__ void init_kernel(){
    int i = blockIdx.x * blockDim.x + threadIdx.x;
    if (i < H_ * B_) g_hT0[i] = 0.0f;
    if (i < 8 * 64 * 32){
        g_hfrag[0][i] = make_uint4(0u, 0u, 0u, 0u);
        g_hfrag[1][i] = make_uint4(0u, 0u, 0u, 0u);
    }
    if (i < 8 * 32){ g_sub2[0][i] = 0u; g_sub2[1][i] = 0u; }
    if (i < 2 * 32){ g_master2[i] = 0u; g_phase2[i] = 0u; }
}

__global__ void bhh_copy_kernel(const float* __restrict__ bhh){
    int i = blockIdx.x * 256 + threadIdx.x;
    if (i < H3_) g_bhh[i] = bhh[i];
}

// ---------------- W_hh -> fragment layout (hi/lo bf16 planes) ----------------
__global__ void wfrag_kernel(const float* __restrict__ Whh){
    int gid = blockIdx.x * 256 + threadIdx.x;
    int lane = gid & 31;
    int tile = gid >> 5;
    if (tile >= 64 * 3 * 64) return;
    int ktg = tile & 63;
    int mt  = (tile >> 6) % 3;
    int cg  = tile / 192;
    int c0  = cg * 16;
    int row0 = mt * H_ + c0;
    int j = lane >> 2;
    int k = ktg * 16 + (lane & 3) * 2;

    const float* W = Whh;
    float w00 = W[(size_t)(row0 + j    ) * H_ + k    ];
    float w01 = W[(size_t)(row0 + j    ) * H_ + k + 1];
    float w10 = W[(size_t)(row0 + j + 8) * H_ + k    ];
    float w11 = W[(size_t)(row0 + j + 8) * H_ + k + 1];
    float w02 = W[(size_t)(row0 + j    ) * H_ + k + 8];
    float w03 = W[(size_t)(row0 + j    ) * H_ + k + 9];
    float w12 = W[(size_t)(row0 + j + 8) * H_ + k + 8];
    float w13 = W[(size_t)(row0 + j + 8) * H_ + k + 9];

    uint4 hi, lo;
    hi.x = pack_bf2(w00, w01); hi.y = pack_bf2(w10, w11);
    hi.z = pack_bf2(w02, w03); hi.w = pack_bf2(w12, w13);
    lo.x = pack_bf2(w00 - bf2f(f2bf(w00)), w01 - bf2f(f2bf(w01)));
    lo.y = pack_bf2(w10 - bf2f(f2bf(w10)), w11 - bf2f(f2bf(w11)));
    lo.z = pack_bf2(w02 - bf2f(f2bf(w02)), w03 - bf2f(f2bf(w03)));
    lo.w = pack_bf2(w12 - bf2f(f2bf(w12)), w13 - bf2f(f2bf(w13)));

    g_wfrag[(size_t)tile * 64 + lane * 2    ] = hi;
    g_wfrag[(size_t)tile * 64 + lane * 2 + 1] = lo;
}

// ---------------- GI = in_seq @ W_ih^T + b_ih (passing form) ----------------
__global__ __launch_bounds__(256) void gi_kernel(const float* __restrict__ x,
                                                 const float* __restrict__ Wih,
                                                 const float* __restrict__ bih)
{
    __shared__ __align__(16) float  As[16][72];
    __shared__ __align__(16) float2 Bsd[16][66];

    const int tid = threadIdx.x;
    const int tx = tid & 15;
    const int ty = tid >> 4;
    const int lrow = tid >> 2;
    const int lkq = tid & 3;
    const int t  = blockIdx.y;
    const int j0 = blockIdx.x * 64;

    const float* arow = x   + (size_t)lrow * (T_ * IN_) + (size_t)t * IN_;
    const float* brow = Wih + (size_t)(j0 + lrow) * IN_;

    u64 acc[4][2];
    #pragma unroll
    for (int j = 0; j < 4; j++){ acc[j][0] = 0ull; acc[j][1] = 0ull; }

    for (int k0 = 0; k0 < IN_; k0 += 16){
        float4 av = *(const float4*)(arow + k0 + lkq * 4);
        float4 bv = *(const float4*)(brow + k0 + lkq * 4);
        As[lkq*4+0][lrow] = av.x; As[lkq*4+1][lrow] = av.y;
        As[lkq*4+2][lrow] = av.z; As[lkq*4+3][lrow] = av.w;
        Bsd[lkq*4+0][lrow] = make_float2(bv.x, bv.x);
        Bsd[lkq*4+1][lrow] = make_float2(bv.y, bv.y);
        Bsd[lkq*4+2][lrow] = make_float2(bv.z, bv.z);
        Bsd[lkq*4+3][lrow] = make_float2(bv.w, bv.w);
        __syncthreads();
        #pragma unroll
        for (int kk = 0; kk < 16; kk++){
            ulonglong2 a   = *(const ulonglong2*)&As[kk][ty * 4];
            ulonglong2 b01 = *(const ulonglong2*)&Bsd[kk][tx * 4];
            ulonglong2 b23 = *(const ulonglong2*)&Bsd[kk][tx * 4 + 2];
            FMA2(acc[0][0], a.x, b01.x); FMA2(acc[0][1], a.y, b01.x);
            FMA2(acc[1][0], a.x, b01.y); FMA2(acc[1][1], a.y, b01.y);
            FMA2(acc[2][0], a.x, b23.x); FMA2(acc[2][1], a.y, b23.x);
            FMA2(acc[3][0], a.x, b23.y); FMA2(acc[3][1], a.y, b23.y);
        }
        __syncthreads();
    }

    float4 bias = *(const float4*)(bih + j0 + tx * 4);
    #pragma unroll
    for (int p = 0; p < 2; p++){
        int m0 = ty * 4 + 2 * p;
        float4 v0;
        float4 v1;
        v0.x = lo32(acc[0][p]) + bias.x; v0.y = lo32(acc[1][p]) + bias.y;
        v0.z = lo32(acc[2][p]) + bias.z; v0.w = lo32(acc[3][p]) + bias.w;
        v1.x = hi32(acc[0][p]) + bias.x; v1.y = hi32(acc[1][p]) + bias.y;
        v1.z = hi32(acc[2][p]) + bias.z; v1.w = hi32(acc[3][p]) + bias.w;
        *(float4*)&g_gi[(size_t)(t * B_ + m0    ) * H3_ + j0 + tx * 4] = v0;
        *(float4*)&g_gi[(size_t)(t * B_ + m0 + 1) * H3_ + j0 + tx * 4] = v1;
    }
}

// ---------------- per-half two-level grid barrier (monotonic counters) ----------------
static __device__ __forceinline__ void grid_bar(int tid, int blk, unsigned target){
    __threadfence();
    __syncthreads();
    if (tid == 0){
        const int half = blk & 1;
        const int grp  = (blk >> 1) >> 3;
        unsigned a;
        asm volatile("atom.acq_rel.gpu.global.add.u32 %0, [%1], %2;"
                     : "=r"(a) : "l"(&g_sub2[half][grp * 32]), "r"(1u) : "memory");
        bool released = false;
        if (a + 1u == 8u * target){
            unsigned m;
            asm volatile("atom.acq_rel.gpu.global.add.u32 %0, [%1], %2;"
                         : "=r"(m) : "l"(&g_master2[half * 32]), "r"(1u) : "memory");
            if (m + 1u == 8u * target){
                asm volatile("st.release.gpu.global.u32 [%0], %1;"
                             :: "l"(&g_phase2[half * 32]), "r"(target) : "memory");
                released = true;
            }
        }
        if (!released){
            unsigned pcur;
            do {
                asm volatile("ld.acquire.gpu.global.u32 %0, [%1];"
                             : "=r"(pcur) : "l"(&g_phase2[half * 32]) : "memory");
            } while (pcur < target);
        }
    }
    __syncthreads();
}

// ---------------- persistent HMMA recurrence (128 blocks, 2 independent halves) ----------------
__global__ __launch_bounds__(256, 1) void gru_mma()
{
    extern __shared__ float red[];   // [3 gates][8 warps][WPAD words]

    const int tid = threadIdx.x;
    const int w   = tid >> 5;
    const int l   = tid & 31;
    const int blk = blockIdx.x;
    const int cg  = blk >> 1;          // column group (W rows / produced h-frag k-tile)
    const int c0  = cg * 16;
    const int nb0 = (blk & 1) * 32;    // batch base
    const int ntb = (blk & 1) * 4;     // batch-tile base

    // gate-phase decode
    const int gntl = tid >> 6;           // 0..3
    const int grem = tid & 63;
    const int gjj  = grem >> 3;          // 0..7
    const int gnc  = grem & 7;           // 0..7
    const int gn   = nb0 + gntl * 8 + gnc;
    const int lane_r = gjj * 4 + (gnc >> 1);
    const int rp   = gnc & 1;

    const float bhr0 = g_bhh[c0 + gjj];
    const float bhr1 = g_bhh[c0 + gjj + 8];
    const float bhz0 = g_bhh[H_ + c0 + gjj];
    const float bhz1 = g_bhh[H_ + c0 + gjj + 8];
    const float bhn0 = g_bhh[2 * H_ + c0 + gjj];
    const float bhn1 = g_bhh[2 * H_ + c0 + gjj + 8];

    float hold0 = 0.0f;   // h(c0+gjj,   gn), register-resident across steps
    float hold1 = 0.0f;   // h(c0+gjj+8, gn)

    const uint4* wf = g_wfrag;
    unsigned bar_t = 0;

    #pragma unroll 1
    for (int t = 0; t < T_; t++){
        const uint4* hfr = g_hfrag[t & 1];
        uint4* hfw4 = &g_hfrag[(t + 1) & 1][0];

        // prefetch gi (consumed after the MMA phase)
        const float* gA = g_gi + ((size_t)t * B_ + gn) * H3_ + c0 + gjj;
        float gir0 = gA[0],      gir1 = gA[8];
        float giz0 = gA[H_],     giz1 = gA[H_ + 8];
        float gin0 = gA[2 * H_], gin1 = gA[2 * H_ + 8];

        // ---- MMA phase: warp owns k-slice [w*8, w*8+8), 3 mt x 4 nt ----
        float C[3][4][4];
        #pragma unroll
        for (int mt = 0; mt < 3; mt++)
            #pragma unroll
            for (int nt = 0; nt < 4; nt++)
                #pragma unroll
                for (int r = 0; r < 4; r++) C[mt][nt][r] = 0.0f;

        #pragma unroll 2
        for (int kt = 0; kt < 8; kt++){
            const int ktg = w * 8 + kt;
            uint4 Ah[3], Al[3];
            #pragma unroll
            for (int mt = 0; mt < 3; mt++){
                size_t ti = ((size_t)(cg * 3 + mt) * 64 + ktg) * 64 + l * 2;
                Ah[mt] = wf[ti];
                Al[mt] = wf[ti + 1];
            }
            uint4 Bv[4];
            #pragma unroll
            for (int nt = 0; nt < 4; nt++)
                Bv[nt] = __ldcg(&hfr[(size_t)((ntb + nt) * 64 + ktg) * 32 + l]);

            #pragma unroll
            for (int mt = 0; mt < 3; mt++){
                #pragma unroll
                for (int nt = 0; nt < 4; nt++){
                    MMA_BF16(C[mt][nt], Ah[mt], Bv[nt].x, Bv[nt].y);  // Wh*Hh
                    MMA_BF16(C[mt][nt], Ah[mt], Bv[nt].z, Bv[nt].w);  // Wh*Hl
                    MMA_BF16(C[mt][nt], Al[mt], Bv[nt].x, Bv[nt].y);  // Wl*Hh
                }
            }
        }

        // ---- store partials (conflict-free STS.128) ----
        #pragma unroll
        for (int mt = 0; mt < 3; mt++){
            #pragma unroll
            for (int nt = 0; nt < 4; nt++){
                int wordu = (mt * 8 + w) * WPAD + (nt * 32 + l) * 4;
                *(float4*)&red[wordu] = make_float4(C[mt][nt][0], C[mt][nt][1],
                                                    C[mt][nt][2], C[mt][nt][3]);
            }
        }
        __syncthreads();

        // ---- cross-warp reduce (8 partials) + gates ----
        float gh0[3], gh1[3];
        #pragma unroll
        for (int g = 0; g < 3; g++){
            float4 s = make_float4(0.f, 0.f, 0.f, 0.f);
            #pragma unroll
            for (int wv = 0; wv < 8; wv++){
                float4 v = *(const float4*)&red[(g * 8 + wv) * WPAD + (gntl * 32 + lane_r) * 4];
                s.x += v.x; s.y += v.y; s.z += v.z; s.w += v.w;
            }
            gh0[g] = rp ? s.y : s.x;
            gh1[g] = rp ? s.w : s.z;
        }

        float r0 = sigmoidf_(gir0 + gh0[0] + bhr0);
        float z0 = sigmoidf_(giz0 + gh0[1] + bhz0);
        float n0 = tanhf_(gin0 + r0 * (gh0[2] + bhn0));
        float hn0 = (1.0f - z0) * n0 + z0 * hold0;
        hold0 = hn0;

        float r1 = sigmoidf_(gir1 + gh1[0] + bhr1);
        float z1 = sigmoidf_(giz1 + gh1[1] + bhz1);
        float n1 = tanhf_(gin1 + r1 * (gh1[2] + bhn1));
        float hn1 = (1.0f - z1) * n1 + z1 * hold1;
        hold1 = hn1;

        // ---- coalesced bf16 hi/lo fragment writeback (pair-exchange, STG.128) ----
        {
            unsigned x0 = f2bf(hn0);
            unsigned x1 = f2bf(hn0 - bf2f(x0));
            unsigned x2 = f2bf(hn1);
            unsigned x3 = f2bf(hn1 - bf2f(x2));
            unsigned p0 = __shfl_xor_sync(0xffffffffu, x0, 8);
            unsigned p1 = __shfl_xor_sync(0xffffffffu, x1, 8);
            unsigned p2 = __shfl_xor_sync(0xffffffffu, x2, 8);
            unsigned p3 = __shfl_xor_sync(0xffffffffu, x3, 8);
            if ((gjj & 1) == 0){
                int lb = gnc * 4 + (gjj >> 1);
                uint4 v;
                v.x = x0 | (p0 << 16);   // hi b0: even, odd
                v.y = x2 | (p2 << 16);   // hi b1
                v.z = x1 | (p1 << 16);   // lo b0
                v.w = x3 | (p3 << 16);   // lo b1
                hfw4[((size_t)(ntb + gntl) * 64 + cg) * 32 + lb] = v;
            }
        }

        if (t == T_ - 1){
            g_hT0[(size_t)(c0 + gjj    ) * B_ + gn] = hn0;
            g_hT0[(size_t)(c0 + gjj + 8) * B_ + gn] = hn1;
        }

        bar_t += 1u;
        grid_bar(tid, blk, bar_t);
    }
}

// ---------------- logits = h_final @ W_dense^T + b_dense ----------------
__global__ __launch_bounds__(256) void dense_kernel(const float* __restrict__ Wd,
                                                    const float* __restrict__ bd,
                                                    float* __restrict__ out)
{
    __shared__ __align__(16) float  As[16][72];
    __shared__ __align__(16) float2 Bsd[16][66];

    const int tid = threadIdx.x;
    const int tx = tid & 15;
    const int ty = tid >> 4;
    const int lrow = tid >> 2;
    const int lkq = tid & 3;
    const int kk_ld = tid >> 4;
    const int bq_ld = (tid & 15) * 4;
    const int j0 = blockIdx.x * 64;

    const int jrow = j0 + lrow;
    const bool jok = (jrow < OUT_);
    const float* brow = Wd + (size_t)(jok ? jrow : 0) * H_;

    u64 acc[4][2];
    #pragma unroll
    for (int j = 0; j < 4; j++){ acc[j][0] = 0ull; acc[j][1] = 0ull; }

    for (int k0 = 0; k0 < H_; k0 += 16){
        float4 av = *(const float4*)(g_hT0 + (size_t)(k0 + kk_ld) * B_ + bq_ld);
        float4 bv = make_float4(0.f, 0.f, 0.f, 0.f);
        if (jok) bv = *(const float4*)(brow + k0 + lkq * 4);
        *(float4*)&As[kk_ld][bq_ld] = av;
        Bsd[lkq*4+0][lrow] = make_float2(bv.x, bv.x);
        Bsd[lkq*4+1][lrow] = make_float2(bv.y, bv.y);
        Bsd[lkq*4+2][lrow] = make_float2(bv.z, bv.z);
        Bsd[lkq*4+3][lrow] = make_float2(bv.w, bv.w);
        __syncthreads();
        #pragma unroll
        for (int kk = 0; kk < 16; kk++){
            ulonglong2 a   = *(const ulonglong2*)&As[kk][ty * 4];
            ulonglong2 b01 = *(const ulonglong2*)&Bsd[kk][tx * 4];
            ulonglong2 b23 = *(const ulonglong2*)&Bsd[kk][tx * 4 + 2];
            FMA2(acc[0][0], a.x, b01.x); FMA2(acc[0][1], a.y, b01.x);
            FMA2(acc[1][0], a.x, b01.y); FMA2(acc[1][1], a.y, b01.y);
            FMA2(acc[2][0], a.x, b23.x); FMA2(acc[2][1], a.y, b23.x);
            FMA2(acc[3][0], a.x, b23.y); FMA2(acc[3][1], a.y, b23.y);
        }
        __syncthreads();
    }

    #pragma unroll
    for (int p = 0; p < 2; p++){
        #pragma unroll
        for (int half = 0; half < 2; half++){
            int m = ty * 4 + 2 * p + half;
            #pragma unroll
            for (int jj = 0; jj < 4; jj++){
                int col = j0 + tx * 4 + jj;
                if (col < OUT_){
                    float v = half ? hi32(acc[jj][p]) : lo32(acc[jj][p]);
                    out[(size_t)m * OUT_ + col] = v + bd[col];
                }
            }
        }
    }
}

// ---------------- in-place row-wise log_softmax ----------------
__global__ __launch_bounds__(256) void lsm_kernel(float* __restrict__ out)
{
    __shared__ float red[256];
    const int tid = threadIdx.x;
    float* row = out + (size_t)blockIdx.x * OUT_;

    float m = -1e30f;
    for (int i = tid; i < OUT_; i += 256) m = fmaxf(m, row[i]);
    red[tid] = m; __syncthreads();
    for (int s = 128; s > 0; s >>= 1){
        if (tid < s) red[tid] = fmaxf(red[tid], red[tid + s]);
        __syncthreads();
    }
    float M = red[0];
    __syncthreads();

    float sm = 0.0f;
    for (int i = tid; i < OUT_; i += 256) sm += expf(row[i] - M);
    red[tid] = sm; __syncthreads();
    for (int s = 128; s > 0; s >>= 1){
        if (tid < s) red[tid] += red[tid + s];
        __syncthreads();
    }
    float L = M + logf(red[0]);
    for (int i = tid; i < OUT_; i += 256) row[i] -= L;
}

// ---------------- launch ----------------
extern "C" void kernel_launch(void* const* d_in, const int* in_sizes, int n_in,
                              void* d_out, int out_size)
{
    const float* x    = (const float*)d_in[0];
    const float* Wih  = (const float*)d_in[1];
    const float* Whh  = (const float*)d_in[2];
    const float* bih  = (const float*)d_in[3];
    const float* bhh  = (const float*)d_in[4];
    const float* Wd   = (const float*)d_in[5];
    const float* bd   = (const float*)d_in[6];
    float* out = (float*)d_out;

    const size_t smem_bytes = (size_t)3 * 8 * WPAD * sizeof(float);  // 49536
    cudaFuncSetAttribute(gru_mma, cudaFuncAttributeMaxDynamicSharedMemorySize,
                         (int)smem_bytes);

    init_kernel<<<64, 1024>>>();
    bhh_copy_kernel<<<(H3_ + 255) / 256, 256>>>(bhh);
    wfrag_kernel<<<1536, 256>>>(Whh);
    gi_kernel<<<dim3(48, T_), 256>>>(x, Wih, bih);
    gru_mma<<<NB, 256, smem_bytes>>>();
    dense_kernel<<<(OUT_ + 63) / 64, 256>>>(Wd, bd, out);
    lsm_kernel<<<B_, 256>>>(out);
}

// round 13
// speedup vs baseline: 4.1073x; 1.5946x over previous
#include <cuda_runtime.h>
#include <math.h>
#include <cstdint>

#define T_    512
#define B_    64
#define IN_   256
#define H_    1024
#define H3_   3072
#define OUT_  50257

#define NB    128         // persistent blocks; block = 16 cols x 32 batches
#define WPAD  516         // padded word stride per (gate,warp) slice

// ---------------- device scratch ----------------
__device__ float g_gi[(size_t)T_ * B_ * H3_];    // [T][B][3H]
__device__ float g_hT0[H_ * B_];                 // h fp32 [col][b] (written at final step)
__device__ uint4 g_wfrag[64 * 3 * 64 * 32 * 2];  // W_hh frags
__device__ uint4 g_hfrag[2][8 * 64 * 32];        // h frags, double-buffered
__device__ uint4 g_wihfrag[192 * 16 * 64];       // W_ih frags: [(mtg*16+ktg)][lane][hi|lo]
__device__ uint4 g_xfrag[(size_t)4096 * 16 * 32];// x frags: [(nt*16+ktg)*32+lane]
__device__ float g_bhh[H3_];
__device__ unsigned g_sub2[2][8 * 32];
__device__ unsigned g_master2[2 * 32];
__device__ unsigned g_phase2[2 * 32];

typedef unsigned long long u64;

#define FMA2(acc, a, b) asm("fma.rn.f32x2 %0, %1, %2, %0;" : "+l"(acc) : "l"(a), "l"(b))

static __device__ __forceinline__ float lo32(u64 v){ return __uint_as_float((unsigned)(v & 0xffffffffull)); }
static __device__ __forceinline__ float hi32(u64 v){ return __uint_as_float((unsigned)(v >> 32)); }
static __device__ __forceinline__ float sigmoidf_(float x){ return 1.0f / (1.0f + expf(-x)); }
static __device__ __forceinline__ float tanhf_(float x){
    float e = expf(-2.0f * fabsf(x));
    float t = (1.0f - e) / (1.0f + e);
    return copysignf(t, x);
}

// manual bf16 round-to-nearest-even
static __device__ __forceinline__ unsigned f2bf(float f){
    unsigned u = __float_as_uint(f);
    unsigned r = u + 0x7FFFu + ((u >> 16) & 1u);
    return (r >> 16) & 0xFFFFu;
}
static __device__ __forceinline__ float bf2f(unsigned s){
    return __uint_as_float(s << 16);
}
static __device__ __forceinline__ unsigned pack_bf2(float a, float b){
    return f2bf(a) | (f2bf(b) << 16);
}

// mma.sync bf16: D = A(16x16) * B(16x8) + D
#define MMA_BF16(C, A, b0v, b1v) \
    asm volatile("mma.sync.aligned.m16n8k16.row.col.f32.bf16.bf16.f32 " \
        "{%0,%1,%2,%3}, {%4,%5,%6,%7}, {%8,%9}, {%0,%1,%2,%3};" \
        : "+f"((C)[0]), "+f"((C)[1]), "+f"((C)[2]), "+f"((C)[3]) \
        : "r"((A).x), "r"((A).y), "r"((A).z), "r"((A).w), "r"(b0v), "r"(b1v))

// ---------------- init ----------------
__global__ void init_kernel(){
    int i = blockIdx.x * blockDim.x + threadIdx.x;
    if (i < H_ * B_) g_hT0[i] = 0.0f;
    if (i < 8 * 64 * 32){
        g_hfrag[0][i] = make_uint4(0u, 0u, 0u, 0u);
        g_hfrag[1][i] = make_uint4(0u, 0u, 0u, 0u);
    }
    if (i < 8 * 32){ g_sub2[0][i] = 0u; g_sub2[1][i] = 0u; }
    if (i < 2 * 32){ g_master2[i] = 0u; g_phase2[i] = 0u; }
}

__global__ void bhh_copy_kernel(const float* __restrict__ bhh){
    int i = blockIdx.x * 256 + threadIdx.x;
    if (i < H3_) g_bhh[i] = bhh[i];
}

// ---------------- W_hh -> fragment layout ----------------
__global__ void wfrag_kernel(const float* __restrict__ Whh){
    int gid = blockIdx.x * 256 + threadIdx.x;
    int lane = gid & 31;
    int tile = gid >> 5;
    if (tile >= 64 * 3 * 64) return;
    int ktg = tile & 63;
    int mt  = (tile >> 6) % 3;
    int cg  = tile / 192;
    int c0  = cg * 16;
    int row0 = mt * H_ + c0;
    int j = lane >> 2;
    int k = ktg * 16 + (lane & 3) * 2;

    const float* W = Whh;
    float w00 = W[(size_t)(row0 + j    ) * H_ + k    ];
    float w01 = W[(size_t)(row0 + j    ) * H_ + k + 1];
    float w10 = W[(size_t)(row0 + j + 8) * H_ + k    ];
    float w11 = W[(size_t)(row0 + j + 8) * H_ + k + 1];
    float w02 = W[(size_t)(row0 + j    ) * H_ + k + 8];
    float w03 = W[(size_t)(row0 + j    ) * H_ + k + 9];
    float w12 = W[(size_t)(row0 + j + 8) * H_ + k + 8];
    float w13 = W[(size_t)(row0 + j + 8) * H_ + k + 9];

    uint4 hi, lo;
    hi.x = pack_bf2(w00, w01); hi.y = pack_bf2(w10, w11);
    hi.z = pack_bf2(w02, w03); hi.w = pack_bf2(w12, w13);
    lo.x = pack_bf2(w00 - bf2f(f2bf(w00)), w01 - bf2f(f2bf(w01)));
    lo.y = pack_bf2(w10 - bf2f(f2bf(w10)), w11 - bf2f(f2bf(w11)));
    lo.z = pack_bf2(w02 - bf2f(f2bf(w02)), w03 - bf2f(f2bf(w03)));
    lo.w = pack_bf2(w12 - bf2f(f2bf(w12)), w13 - bf2f(f2bf(w13)));

    g_wfrag[(size_t)tile * 64 + lane * 2    ] = hi;
    g_wfrag[(size_t)tile * 64 + lane * 2 + 1] = lo;
}

// ---------------- W_ih -> fragment layout ----------------
__global__ void wihfrag_kernel(const float* __restrict__ Wih){
    int gid = blockIdx.x * 256 + threadIdx.x;
    int lane = gid & 31;
    int tile = gid >> 5;
    if (tile >= 192 * 16) return;
    int ktg = tile & 15;
    int mtg = tile >> 4;
    int row0 = mtg * 16;
    int j = lane >> 2;
    int k = ktg * 16 + (lane & 3) * 2;

    const float* W = Wih;
    float w00 = W[(size_t)(row0 + j    ) * IN_ + k    ];
    float w01 = W[(size_t)(row0 + j    ) * IN_ + k + 1];
    float w10 = W[(size_t)(row0 + j + 8) * IN_ + k    ];
    float w11 = W[(size_t)(row0 + j + 8) * IN_ + k + 1];
    float w02 = W[(size_t)(row0 + j    ) * IN_ + k + 8];
    float w03 = W[(size_t)(row0 + j    ) * IN_ + k + 9];
    float w12 = W[(size_t)(row0 + j + 8) * IN_ + k + 8];
    float w13 = W[(size_t)(row0 + j + 8) * IN_ + k + 9];

    uint4 hi, lo;
    hi.x = pack_bf2(w00, w01); hi.y = pack_bf2(w10, w11);
    hi.z = pack_bf2(w02, w03); hi.w = pack_bf2(w12, w13);
    lo.x = pack_bf2(w00 - bf2f(f2bf(w00)), w01 - bf2f(f2bf(w01)));
    lo.y = pack_bf2(w10 - bf2f(f2bf(w10)), w11 - bf2f(f2bf(w11)));
    lo.z = pack_bf2(w02 - bf2f(f2bf(w02)), w03 - bf2f(f2bf(w03)));
    lo.w = pack_bf2(w12 - bf2f(f2bf(w12)), w13 - bf2f(f2bf(w13)));

    g_wihfrag[(size_t)tile * 64 + lane * 2    ] = hi;
    g_wihfrag[(size_t)tile * 64 + lane * 2 + 1] = lo;
}

// ---------------- x -> B-fragment layout (bt row = t*64+b) ----------------
__global__ void xfrag_kernel(const float* __restrict__ x){
    int gid = blockIdx.x * 256 + threadIdx.x;
    int lane = gid & 31;
    int t16 = gid >> 5;
    if (t16 >= 4096 * 16) return;
    int ktg = t16 & 15;
    int nt  = t16 >> 4;
    int n = nt * 8 + (lane >> 2);          // bt row
    int k = ktg * 16 + (lane & 3) * 2;
    int b = n & 63;
    int t = n >> 6;
    const float* xr = x + ((size_t)b * T_ + t) * IN_;
    float f0 = xr[k], f1 = xr[k + 1], f2 = xr[k + 8], f3 = xr[k + 9];
    uint4 v;
    v.x = pack_bf2(f0, f1);
    v.y = pack_bf2(f2, f3);
    v.z = pack_bf2(f0 - bf2f(f2bf(f0)), f1 - bf2f(f2bf(f1)));
    v.w = pack_bf2(f2 - bf2f(f2bf(f2)), f3 - bf2f(f2bf(f3)));
    g_xfrag[(size_t)t16 * 32 + lane] = v;
}

// ---------------- GI via HMMA: gi = x @ Wih^T + b_ih ----------------
__global__ __launch_bounds__(256) void gi_mma(const float* __restrict__ bih){
    const int tid = threadIdx.x;
    const int w = tid >> 5;
    const int l = tid & 31;
    const int mtg = blockIdx.y * 4 + (w >> 1);     // 16-col tile of 3072
    const int ntb = blockIdx.x * 8 + (w & 1) * 4;  // base 8-row bt tile

    float C[4][4];
    #pragma unroll
    for (int q = 0; q < 4; q++)
        #pragma unroll
        for (int r = 0; r < 4; r++) C[q][r] = 0.0f;

    #pragma unroll 4
    for (int ktg = 0; ktg < 16; ktg++){
        size_t ai = ((size_t)mtg * 16 + ktg) * 64 + l * 2;
        uint4 Ah = g_wihfrag[ai];
        uint4 Al = g_wihfrag[ai + 1];
        uint4 Bv[4];
        #pragma unroll
        for (int q = 0; q < 4; q++)
            Bv[q] = g_xfrag[((size_t)(ntb + q) * 16 + ktg) * 32 + l];
        #pragma unroll
        for (int q = 0; q < 4; q++){
            MMA_BF16(C[q], Ah, Bv[q].x, Bv[q].y);
            MMA_BF16(C[q], Ah, Bv[q].z, Bv[q].w);
            MMA_BF16(C[q], Al, Bv[q].x, Bv[q].y);
        }
    }

    const int col0 = mtg * 16 + (l >> 2);
    const int col1 = col0 + 8;
    const float b0 = bih[col0];
    const float b1 = bih[col1];
    #pragma unroll
    for (int q = 0; q < 4; q++){
        int n = (ntb + q) * 8 + (l & 3) * 2;
        g_gi[(size_t)n       * H3_ + col0] = C[q][0] + b0;
        g_gi[(size_t)(n + 1) * H3_ + col0] = C[q][1] + b0;
        g_gi[(size_t)n       * H3_ + col1] = C[q][2] + b1;
        g_gi[(size_t)(n + 1) * H3_ + col1] = C[q][3] + b1;
    }
}

// ---------------- per-half two-level grid barrier ----------------
static __device__ __forceinline__ void grid_bar(int tid, int blk, unsigned target){
    __threadfence();
    __syncthreads();
    if (tid == 0){
        const int half = blk & 1;
        const int grp  = (blk >> 1) >> 3;
        unsigned a;
        asm volatile("atom.acq_rel.gpu.global.add.u32 %0, [%1], %2;"
                     : "=r"(a) : "l"(&g_sub2[half][grp * 32]), "r"(1u) : "memory");
        bool released = false;
        if (a + 1u == 8u * target){
            unsigned m;
            asm volatile("atom.acq_rel.gpu.global.add.u32 %0, [%1], %2;"
                         : "=r"(m) : "l"(&g_master2[half * 32]), "r"(1u) : "memory");
            if (m + 1u == 8u * target){
                asm volatile("st.release.gpu.global.u32 [%0], %1;"
                             :: "l"(&g_phase2[half * 32]), "r"(target) : "memory");
                released = true;
            }
        }
        if (!released){
            unsigned pcur;
            do {
                asm volatile("ld.acquire.gpu.global.u32 %0, [%1];"
                             : "=r"(pcur) : "l"(&g_phase2[half * 32]) : "memory");
            } while (pcur < target);
        }
    }
    __syncthreads();
}

// ---------------- persistent HMMA recurrence ----------------
__global__ __launch_bounds__(256, 1) void gru_mma()
{
    extern __shared__ float red[];

    const int tid = threadIdx.x;
    const int w   = tid >> 5;
    const int l   = tid & 31;
    const int blk = blockIdx.x;
    const int cg  = blk >> 1;
    const int c0  = cg * 16;
    const int nb0 = (blk & 1) * 32;
    const int ntb = (blk & 1) * 4;

    const int gntl = tid >> 6;
    const int grem = tid & 63;
    const int gjj  = grem >> 3;
    const int gnc  = grem & 7;
    const int gn   = nb0 + gntl * 8 + gnc;
    const int lane_r = gjj * 4 + (gnc >> 1);
    const int rp   = gnc & 1;

    const float bhr0 = g_bhh[c0 + gjj];
    const float bhr1 = g_bhh[c0 + gjj + 8];
    const float bhz0 = g_bhh[H_ + c0 + gjj];
    const float bhz1 = g_bhh[H_ + c0 + gjj + 8];
    const float bhn0 = g_bhh[2 * H_ + c0 + gjj];
    const float bhn1 = g_bhh[2 * H_ + c0 + gjj + 8];

    float hold0 = 0.0f;
    float hold1 = 0.0f;

    const uint4* wf = g_wfrag;
    unsigned bar_t = 0;

    #pragma unroll 1
    for (int t = 0; t < T_; t++){
        const uint4* hfr = g_hfrag[t & 1];
        uint4* hfw4 = &g_hfrag[(t + 1) & 1][0];

        const float* gA = g_gi + ((size_t)t * B_ + gn) * H3_ + c0 + gjj;
        float gir0 = gA[0],      gir1 = gA[8];
        float giz0 = gA[H_],     giz1 = gA[H_ + 8];
        float gin0 = gA[2 * H_], gin1 = gA[2 * H_ + 8];

        float C[3][4][4];
        #pragma unroll
        for (int mt = 0; mt < 3; mt++)
            #pragma unroll
            for (int nt = 0; nt < 4; nt++)
                #pragma unroll
                for (int r = 0; r < 4; r++) C[mt][nt][r] = 0.0f;

        #pragma unroll 2
        for (int kt = 0; kt < 8; kt++){
            const int ktg = w * 8 + kt;
            uint4 Ah[3], Al[3];
            #pragma unroll
            for (int mt = 0; mt < 3; mt++){
                size_t ti = ((size_t)(cg * 3 + mt) * 64 + ktg) * 64 + l * 2;
                Ah[mt] = wf[ti];
                Al[mt] = wf[ti + 1];
            }
            uint4 Bv[4];
            #pragma unroll
            for (int nt = 0; nt < 4; nt++)
                Bv[nt] = __ldcg(&hfr[(size_t)((ntb + nt) * 64 + ktg) * 32 + l]);

            #pragma unroll
            for (int mt = 0; mt < 3; mt++){
                #pragma unroll
                for (int nt = 0; nt < 4; nt++){
                    MMA_BF16(C[mt][nt], Ah[mt], Bv[nt].x, Bv[nt].y);
                    MMA_BF16(C[mt][nt], Ah[mt], Bv[nt].z, Bv[nt].w);
                    MMA_BF16(C[mt][nt], Al[mt], Bv[nt].x, Bv[nt].y);
                }
            }
        }

        #pragma unroll
        for (int mt = 0; mt < 3; mt++){
            #pragma unroll
            for (int nt = 0; nt < 4; nt++){
                int wordu = (mt * 8 + w) * WPAD + (nt * 32 + l) * 4;
                *(float4*)&red[wordu] = make_float4(C[mt][nt][0], C[mt][nt][1],
                                                    C[mt][nt][2], C[mt][nt][3]);
            }
        }
        __syncthreads();

        float gh0[3], gh1[3];
        #pragma unroll
        for (int g = 0; g < 3; g++){
            float4 s = make_float4(0.f, 0.f, 0.f, 0.f);
            #pragma unroll
            for (int wv = 0; wv < 8; wv++){
                float4 v = *(const float4*)&red[(g * 8 + wv) * WPAD + (gntl * 32 + lane_r) * 4];
                s.x += v.x; s.y += v.y; s.z += v.z; s.w += v.w;
            }
            gh0[g] = rp ? s.y : s.x;
            gh1[g] = rp ? s.w : s.z;
        }

        float r0 = sigmoidf_(gir0 + gh0[0] + bhr0);
        float z0 = sigmoidf_(giz0 + gh0[1] + bhz0);
        float n0 = tanhf_(gin0 + r0 * (gh0[2] + bhn0));
        float hn0 = (1.0f - z0) * n0 + z0 * hold0;
        hold0 = hn0;

        float r1 = sigmoidf_(gir1 + gh1[0] + bhr1);
        float z1 = sigmoidf_(giz1 + gh1[1] + bhz1);
        float n1 = tanhf_(gin1 + r1 * (gh1[2] + bhn1));
        float hn1 = (1.0f - z1) * n1 + z1 * hold1;
        hold1 = hn1;

        {
            unsigned x0 = f2bf(hn0);
            unsigned x1 = f2bf(hn0 - bf2f(x0));
            unsigned x2 = f2bf(hn1);
            unsigned x3 = f2bf(hn1 - bf2f(x2));
            unsigned p0 = __shfl_xor_sync(0xffffffffu, x0, 8);
            unsigned p1 = __shfl_xor_sync(0xffffffffu, x1, 8);
            unsigned p2 = __shfl_xor_sync(0xffffffffu, x2, 8);
            unsigned p3 = __shfl_xor_sync(0xffffffffu, x3, 8);
            if ((gjj & 1) == 0){
                int lb = gnc * 4 + (gjj >> 1);
                uint4 v;
                v.x = x0 | (p0 << 16);
                v.y = x2 | (p2 << 16);
                v.z = x1 | (p1 << 16);
                v.w = x3 | (p3 << 16);
                hfw4[((size_t)(ntb + gntl) * 64 + cg) * 32 + lb] = v;
            }
        }

        if (t == T_ - 1){
            g_hT0[(size_t)(c0 + gjj    ) * B_ + gn] = hn0;
            g_hT0[(size_t)(c0 + gjj + 8) * B_ + gn] = hn1;
        }

        bar_t += 1u;
        grid_bar(tid, blk, bar_t);
    }
}

// ---------------- logits = h_final @ W_dense^T + b_dense ----------------
__global__ __launch_bounds__(256) void dense_kernel(const float* __restrict__ Wd,
                                                    const float* __restrict__ bd,
                                                    float* __restrict__ out)
{
    __shared__ __align__(16) float  As[16][72];
    __shared__ __align__(16) float2 Bsd[16][66];

    const int tid = threadIdx.x;
    const int tx = tid & 15;
    const int ty = tid >> 4;
    const int lrow = tid >> 2;
    const int lkq = tid & 3;
    const int kk_ld = tid >> 4;
    const int bq_ld = (tid & 15) * 4;
    const int j0 = blockIdx.x * 64;

    const int jrow = j0 + lrow;
    const bool jok = (jrow < OUT_);
    const float* brow = Wd + (size_t)(jok ? jrow : 0) * H_;

    u64 acc[4][2];
    #pragma unroll
    for (int j = 0; j < 4; j++){ acc[j][0] = 0ull; acc[j][1] = 0ull; }

    for (int k0 = 0; k0 < H_; k0 += 16){
        float4 av = *(const float4*)(g_hT0 + (size_t)(k0 + kk_ld) * B_ + bq_ld);
        float4 bv = make_float4(0.f, 0.f, 0.f, 0.f);
        if (jok) bv = *(const float4*)(brow + k0 + lkq * 4);
        *(float4*)&As[kk_ld][bq_ld] = av;
        Bsd[lkq*4+0][lrow] = make_float2(bv.x, bv.x);
        Bsd[lkq*4+1][lrow] = make_float2(bv.y, bv.y);
        Bsd[lkq*4+2][lrow] = make_float2(bv.z, bv.z);
        Bsd[lkq*4+3][lrow] = make_float2(bv.w, bv.w);
        __syncthreads();
        #pragma unroll
        for (int kk = 0; kk < 16; kk++){
            ulonglong2 a   = *(const ulonglong2*)&As[kk][ty * 4];
            ulonglong2 b01 = *(const ulonglong2*)&Bsd[kk][tx * 4];
            ulonglong2 b23 = *(const ulonglong2*)&Bsd[kk][tx * 4 + 2];
            FMA2(acc[0][0], a.x, b01.x); FMA2(acc[0][1], a.y, b01.x);
            FMA2(acc[1][0], a.x, b01.y); FMA2(acc[1][1], a.y, b01.y);
            FMA2(acc[2][0], a.x, b23.x); FMA2(acc[2][1], a.y, b23.x);
            FMA2(acc[3][0], a.x, b23.y); FMA2(acc[3][1], a.y, b23.y);
        }
        __syncthreads();
    }

    #pragma unroll
    for (int p = 0; p < 2; p++){
        #pragma unroll
        for (int half = 0; half < 2; half++){
            int m = ty * 4 + 2 * p + half;
            #pragma unroll
            for (int jj = 0; jj < 4; jj++){
                int col = j0 + tx * 4 + jj;
                if (col < OUT_){
                    float v = half ? hi32(acc[jj][p]) : lo32(acc[jj][p]);
                    out[(size_t)m * OUT_ + col] = v + bd[col];
                }
            }
        }
    }
}

// ---------------- in-place row-wise log_softmax ----------------
__global__ __launch_bounds__(256) void lsm_kernel(float* __restrict__ out)
{
    __shared__ float red[256];
    const int tid = threadIdx.x;
    float* row = out + (size_t)blockIdx.x * OUT_;

    float m = -1e30f;
    for (int i = tid; i < OUT_; i += 256) m = fmaxf(m, row[i]);
    red[tid] = m; __syncthreads();
    for (int s = 128; s > 0; s >>= 1){
        if (tid < s) red[tid] = fmaxf(red[tid], red[tid + s]);
        __syncthreads();
    }
    float M = red[0];
    __syncthreads();

    float sm = 0.0f;
    for (int i = tid; i < OUT_; i += 256) sm += expf(row[i] - M);
    red[tid] = sm; __syncthreads();
    for (int s = 128; s > 0; s >>= 1){
        if (tid < s) red[tid] += red[tid + s];
        __syncthreads();
    }
    float L = M + logf(red[0]);
    for (int i = tid; i < OUT_; i += 256) row[i] -= L;
}

// ---------------- launch ----------------
extern "C" void kernel_launch(void* const* d_in, const int* in_sizes, int n_in,
                              void* d_out, int out_size)
{
    const float* x    = (const float*)d_in[0];
    const float* Wih  = (const float*)d_in[1];
    const float* Whh  = (const float*)d_in[2];
    const float* bih  = (const float*)d_in[3];
    const float* bhh  = (const float*)d_in[4];
    const float* Wd   = (const float*)d_in[5];
    const float* bd   = (const float*)d_in[6];
    float* out = (float*)d_out;

    const size_t smem_bytes = (size_t)3 * 8 * WPAD * sizeof(float);  // 49536
    cudaFuncSetAttribute(gru_mma, cudaFuncAttributeMaxDynamicSharedMemorySize,
                         (int)smem_bytes);

    init_kernel<<<64, 1024>>>();
    bhh_copy_kernel<<<(H3_ + 255) / 256, 256>>>(bhh);
    wfrag_kernel<<<1536, 256>>>(Whh);
    wihfrag_kernel<<<384, 256>>>(Wih);
    xfrag_kernel<<<8192, 256>>>(x);
    gi_mma<<<dim3(512, 48), 256>>>(bih);
    gru_mma<<<NB, 256, smem_bytes>>>();
    dense_kernel<<<(OUT_ + 63) / 64, 256>>>(Wd, bd, out);
    lsm_kernel<<<B_, 256>>>(out);
}

// round 14
// speedup vs baseline: 4.2995x; 1.0468x over previous
#include <cuda_runtime.h>
#include <math.h>
#include <cstdint>

#define T_    512
#define B_    64
#define IN_   256
#define H_    1024
#define H3_   3072
#define OUT_  50257

#define NB    128         // persistent blocks; block = 16 cols x 32 batches
#define WPAD  516         // padded word stride per (gate,slot) slice

// ---------------- device scratch ----------------
__device__ float g_gi[(size_t)T_ * B_ * H3_];    // [T][B][3H]
__device__ float g_hT0[H_ * B_];                 // h fp32 [col][b] (final step only)
__device__ uint4 g_wfrag[64 * 3 * 64 * 32 * 2];  // W_hh frags
__device__ uint4 g_hfrag[2][8 * 64 * 32];        // h frags, double-buffered
__device__ uint4 g_wihfrag[192 * 16 * 64];       // W_ih frags
__device__ uint4 g_xfrag[(size_t)4096 * 16 * 32];// x frags
__device__ float g_bhh[H3_];
__device__ unsigned g_sub2[2][8 * 32];
__device__ unsigned g_master2[2 * 32];
__device__ unsigned g_phase2[2 * 32];

typedef unsigned long long u64;

#define FMA2(acc, a, b) asm("fma.rn.f32x2 %0, %1, %2, %0;" : "+l"(acc) : "l"(a), "l"(b))

static __device__ __forceinline__ float lo32(u64 v){ return __uint_as_float((unsigned)(v & 0xffffffffull)); }
static __device__ __forceinline__ float hi32(u64 v){ return __uint_as_float((unsigned)(v >> 32)); }
static __device__ __forceinline__ float sigmoidf_(float x){ return 1.0f / (1.0f + expf(-x)); }
static __device__ __forceinline__ float tanhf_(float x){
    float e = expf(-2.0f * fabsf(x));
    float t = (1.0f - e) / (1.0f + e);
    return copysignf(t, x);
}

static __device__ __forceinline__ unsigned f2bf(float f){
    unsigned u = __float_as_uint(f);
    unsigned r = u + 0x7FFFu + ((u >> 16) & 1u);
    return (r >> 16) & 0xFFFFu;
}
static __device__ __forceinline__ float bf2f(unsigned s){
    return __uint_as_float(s << 16);
}
static __device__ __forceinline__ unsigned pack_bf2(float a, float b){
    return f2bf(a) | (f2bf(b) << 16);
}

#define MMA_BF16(C, A, b0v, b1v) \
    asm volatile("mma.sync.aligned.m16n8k16.row.col.f32.bf16.bf16.f32 " \
        "{%0,%1,%2,%3}, {%4,%5,%6,%7}, {%8,%9}, {%0,%1,%2,%3};" \
        : "+f"((C)[0]), "+f"((C)[1]), "+f"((C)[2]), "+f"((C)[3]) \
        : "r"((A).x), "r"((A).y), "r"((A).z), "r"((A).w), "r"(b0v), "r"(b1v))

// ---------------- init ----------------
__global__ void init_kernel(){
    int i = blockIdx.x * blockDim.x + threadIdx.x;
    if (i < H_ * B_) g_hT0[i] = 0.0f;
    if (i < 8 * 64 * 32){
        g_hfrag[0][i] = make_uint4(0u, 0u, 0u, 0u);
        g_hfrag[1][i] = make_uint4(0u, 0u, 0u, 0u);
    }
    if (i < 8 * 32){ g_sub2[0][i] = 0u; g_sub2[1][i] = 0u; }
    if (i < 2 * 32){ g_master2[i] = 0u; g_phase2[i] = 0u; }
}

__global__ void bhh_copy_kernel(const float* __restrict__ bhh){
    int i = blockIdx.x * 256 + threadIdx.x;
    if (i < H3_) g_bhh[i] = bhh[i];
}

// ---------------- W_hh -> fragment layout ----------------
__global__ void wfrag_kernel(const float* __restrict__ Whh){
    int gid = blockIdx.x * 256 + threadIdx.x;
    int lane = gid & 31;
    int tile = gid >> 5;
    if (tile >= 64 * 3 * 64) return;
    int ktg = tile & 63;
    int mt  = (tile >> 6) % 3;
    int cg  = tile / 192;
    int c0  = cg * 16;
    int row0 = mt * H_ + c0;
    int j = lane >> 2;
    int k = ktg * 16 + (lane & 3) * 2;

    const float* W = Whh;
    float w00 = W[(size_t)(row0 + j    ) * H_ + k    ];
    float w01 = W[(size_t)(row0 + j    ) * H_ + k + 1];
    float w10 = W[(size_t)(row0 + j + 8) * H_ + k    ];
    float w11 = W[(size_t)(row0 + j + 8) * H_ + k + 1];
    float w02 = W[(size_t)(row0 + j    ) * H_ + k + 8];
    float w03 = W[(size_t)(row0 + j    ) * H_ + k + 9];
    float w12 = W[(size_t)(row0 + j + 8) * H_ + k + 8];
    float w13 = W[(size_t)(row0 + j + 8) * H_ + k + 9];

    uint4 hi, lo;
    hi.x = pack_bf2(w00, w01); hi.y = pack_bf2(w10, w11);
    hi.z = pack_bf2(w02, w03); hi.w = pack_bf2(w12, w13);
    lo.x = pack_bf2(w00 - bf2f(f2bf(w00)), w01 - bf2f(f2bf(w01)));
    lo.y = pack_bf2(w10 - bf2f(f2bf(w10)), w11 - bf2f(f2bf(w11)));
    lo.z = pack_bf2(w02 - bf2f(f2bf(w02)), w03 - bf2f(f2bf(w03)));
    lo.w = pack_bf2(w12 - bf2f(f2bf(w12)), w13 - bf2f(f2bf(w13)));

    g_wfrag[(size_t)tile * 64 + lane * 2    ] = hi;
    g_wfrag[(size_t)tile * 64 + lane * 2 + 1] = lo;
}

// ---------------- W_ih -> fragment layout ----------------
__global__ void wihfrag_kernel(const float* __restrict__ Wih){
    int gid = blockIdx.x * 256 + threadIdx.x;
    int lane = gid & 31;
    int tile = gid >> 5;
    if (tile >= 192 * 16) return;
    int ktg = tile & 15;
    int mtg = tile >> 4;
    int row0 = mtg * 16;
    int j = lane >> 2;
    int k = ktg * 16 + (lane & 3) * 2;

    const float* W = Wih;
    float w00 = W[(size_t)(row0 + j    ) * IN_ + k    ];
    float w01 = W[(size_t)(row0 + j    ) * IN_ + k + 1];
    float w10 = W[(size_t)(row0 + j + 8) * IN_ + k    ];
    float w11 = W[(size_t)(row0 + j + 8) * IN_ + k + 1];
    float w02 = W[(size_t)(row0 + j    ) * IN_ + k + 8];
    float w03 = W[(size_t)(row0 + j    ) * IN_ + k + 9];
    float w12 = W[(size_t)(row0 + j + 8) * IN_ + k + 8];
    float w13 = W[(size_t)(row0 + j + 8) * IN_ + k + 9];

    uint4 hi, lo;
    hi.x = pack_bf2(w00, w01); hi.y = pack_bf2(w10, w11);
    hi.z = pack_bf2(w02, w03); hi.w = pack_bf2(w12, w13);
    lo.x = pack_bf2(w00 - bf2f(f2bf(w00)), w01 - bf2f(f2bf(w01)));
    lo.y = pack_bf2(w10 - bf2f(f2bf(w10)), w11 - bf2f(f2bf(w11)));
    lo.z = pack_bf2(w02 - bf2f(f2bf(w02)), w03 - bf2f(f2bf(w03)));
    lo.w = pack_bf2(w12 - bf2f(f2bf(w12)), w13 - bf2f(f2bf(w13)));

    g_wihfrag[(size_t)tile * 64 + lane * 2    ] = hi;
    g_wihfrag[(size_t)tile * 64 + lane * 2 + 1] = lo;
}

// ---------------- x -> B-fragment layout ----------------
__global__ void xfrag_kernel(const float* __restrict__ x){
    int gid = blockIdx.x * 256 + threadIdx.x;
    int lane = gid & 31;
    int t16 = gid >> 5;
    if (t16 >= 4096 * 16) return;
    int ktg = t16 & 15;
    int nt  = t16 >> 4;
    int n = nt * 8 + (lane >> 2);
    int k = ktg * 16 + (lane & 3) * 2;
    int b = n & 63;
    int t = n >> 6;
    const float* xr = x + ((size_t)b * T_ + t) * IN_;
    float f0 = xr[k], f1 = xr[k + 1], f2 = xr[k + 8], f3 = xr[k + 9];
    uint4 v;
    v.x = pack_bf2(f0, f1);
    v.y = pack_bf2(f2, f3);
    v.z = pack_bf2(f0 - bf2f(f2bf(f0)), f1 - bf2f(f2bf(f1)));
    v.w = pack_bf2(f2 - bf2f(f2bf(f2)), f3 - bf2f(f2bf(f3)));
    g_xfrag[(size_t)t16 * 32 + lane] = v;
}

// ---------------- GI via HMMA ----------------
__global__ __launch_bounds__(256) void gi_mma(const float* __restrict__ bih){
    const int tid = threadIdx.x;
    const int w = tid >> 5;
    const int l = tid & 31;
    const int mtg = blockIdx.y * 4 + (w >> 1);
    const int ntb = blockIdx.x * 8 + (w & 1) * 4;

    float C[4][4];
    #pragma unroll
    for (int q = 0; q < 4; q++)
        #pragma unroll
        for (int r = 0; r < 4; r++) C[q][r] = 0.0f;

    #pragma unroll 4
    for (int ktg = 0; ktg < 16; ktg++){
        size_t ai = ((size_t)mtg * 16 + ktg) * 64 + l * 2;
        uint4 Ah = g_wihfrag[ai];
        uint4 Al = g_wihfrag[ai + 1];
        uint4 Bv[4];
        #pragma unroll
        for (int q = 0; q < 4; q++)
            Bv[q] = g_xfrag[((size_t)(ntb + q) * 16 + ktg) * 32 + l];
        #pragma unroll
        for (int q = 0; q < 4; q++){
            MMA_BF16(C[q], Ah, Bv[q].x, Bv[q].y);
            MMA_BF16(C[q], Ah, Bv[q].z, Bv[q].w);
            MMA_BF16(C[q], Al, Bv[q].x, Bv[q].y);
        }
    }

    const int col0 = mtg * 16 + (l >> 2);
    const int col1 = col0 + 8;
    const float b0 = bih[col0];
    const float b1 = bih[col1];
    #pragma unroll
    for (int q = 0; q < 4; q++){
        int n = (ntb + q) * 8 + (l & 3) * 2;
        g_gi[(size_t)n       * H3_ + col0] = C[q][0] + b0;
        g_gi[(size_t)(n + 1) * H3_ + col0] = C[q][1] + b0;
        g_gi[(size_t)n       * H3_ + col1] = C[q][2] + b1;
        g_gi[(size_t)(n + 1) * H3_ + col1] = C[q][3] + b1;
    }
}

// ---------------- per-half two-level grid barrier ----------------
static __device__ __forceinline__ void grid_bar(int tid, int blk, unsigned target){
    __threadfence();
    __syncthreads();
    if (tid == 0){
        const int half = blk & 1;
        const int grp  = (blk >> 1) >> 3;
        unsigned a;
        asm volatile("atom.acq_rel.gpu.global.add.u32 %0, [%1], %2;"
                     : "=r"(a) : "l"(&g_sub2[half][grp * 32]), "r"(1u) : "memory");
        bool released = false;
        if (a + 1u == 8u * target){
            unsigned m;
            asm volatile("atom.acq_rel.gpu.global.add.u32 %0, [%1], %2;"
                         : "=r"(m) : "l"(&g_master2[half * 32]), "r"(1u) : "memory");
            if (m + 1u == 8u * target){
                asm volatile("st.release.gpu.global.u32 [%0], %1;"
                             :: "l"(&g_phase2[half * 32]), "r"(target) : "memory");
                released = true;
            }
        }
        if (!released){
            unsigned pcur;
            do {
                asm volatile("ld.acquire.gpu.global.u32 %0, [%1];"
                             : "=r"(pcur) : "l"(&g_phase2[half * 32]) : "memory");
            } while (pcur < target);
        }
    }
    __syncthreads();
}

// ---------------- persistent HMMA recurrence ----------------
__global__ __launch_bounds__(256, 1) void gru_mma()
{
    extern __shared__ float red[];   // [3 gates][4 slots][WPAD] = 24768B

    const int tid = threadIdx.x;
    const int w   = tid >> 5;
    const int l   = tid & 31;
    const int blk = blockIdx.x;
    const int cg  = blk >> 1;
    const int c0  = cg * 16;
    const int nb0 = (blk & 1) * 32;
    const int ntb = (blk & 1) * 4;

    const int gntl = tid >> 6;
    const int grem = tid & 63;
    const int gjj  = grem >> 3;
    const int gnc  = grem & 7;
    const int gn   = nb0 + gntl * 8 + gnc;
    const int lane_r = gjj * 4 + (gnc >> 1);
    const int rp   = gnc & 1;

    const float bhr0 = g_bhh[c0 + gjj];
    const float bhr1 = g_bhh[c0 + gjj + 8];
    const float bhz0 = g_bhh[H_ + c0 + gjj];
    const float bhz1 = g_bhh[H_ + c0 + gjj + 8];
    const float bhn0 = g_bhh[2 * H_ + c0 + gjj];
    const float bhn1 = g_bhh[2 * H_ + c0 + gjj + 8];

    float hold0 = 0.0f;
    float hold1 = 0.0f;

    const uint4* wf = g_wfrag;
    unsigned bar_t = 0;

    #pragma unroll 1
    for (int t = 0; t < T_; t++){
        const uint4* hfr = g_hfrag[t & 1];
        uint4* hfw4 = &g_hfrag[(t + 1) & 1][0];

        const float* gA = g_gi + ((size_t)t * B_ + gn) * H3_ + c0 + gjj;
        float gir0 = gA[0],      gir1 = gA[8];
        float giz0 = gA[H_],     giz1 = gA[H_ + 8];
        float gin0 = gA[2 * H_], gin1 = gA[2 * H_ + 8];

        float C[3][4][4];
        #pragma unroll
        for (int mt = 0; mt < 3; mt++)
            #pragma unroll
            for (int nt = 0; nt < 4; nt++)
                #pragma unroll
                for (int r = 0; r < 4; r++) C[mt][nt][r] = 0.0f;

        // ---- MMA phase: B double-buffered one kt ahead ----
        uint4 Bv[2][4];
        {
            const int ktg0 = w * 8;
            #pragma unroll
            for (int nt = 0; nt < 4; nt++)
                Bv[0][nt] = __ldcg(&hfr[(size_t)((ntb + nt) * 64 + ktg0) * 32 + l]);
        }
        #pragma unroll
        for (int kt = 0; kt < 8; kt++){
            const int ktg = w * 8 + kt;
            const int cur = kt & 1;
            if (kt < 7){
                #pragma unroll
                for (int nt = 0; nt < 4; nt++)
                    Bv[cur ^ 1][nt] = __ldcg(&hfr[(size_t)((ntb + nt) * 64 + ktg + 1) * 32 + l]);
            }
            uint4 Ah[3], Al[3];
            #pragma unroll
            for (int mt = 0; mt < 3; mt++){
                size_t ti = ((size_t)(cg * 3 + mt) * 64 + ktg) * 64 + l * 2;
                Ah[mt] = wf[ti];
                Al[mt] = wf[ti + 1];
            }
            #pragma unroll
            for (int mt = 0; mt < 3; mt++){
                #pragma unroll
                for (int nt = 0; nt < 4; nt++){
                    MMA_BF16(C[mt][nt], Ah[mt], Bv[cur][nt].x, Bv[cur][nt].y);
                    MMA_BF16(C[mt][nt], Ah[mt], Bv[cur][nt].z, Bv[cur][nt].w);
                    MMA_BF16(C[mt][nt], Al[mt], Bv[cur][nt].x, Bv[cur][nt].y);
                }
            }
        }

        // ---- two-phase reduction: warps 4-7 store, warps 0-3 accumulate ----
        if (w >= 4){
            #pragma unroll
            for (int mt = 0; mt < 3; mt++){
                #pragma unroll
                for (int nt = 0; nt < 4; nt++){
                    int wordu = (mt * 4 + (w - 4)) * WPAD + (nt * 32 + l) * 4;
                    *(float4*)&red[wordu] = make_float4(C[mt][nt][0], C[mt][nt][1],
                                                        C[mt][nt][2], C[mt][nt][3]);
                }
            }
        }
        __syncthreads();
        if (w < 4){
            #pragma unroll
            for (int mt = 0; mt < 3; mt++){
                #pragma unroll
                for (int nt = 0; nt < 4; nt++){
                    int wordu = (mt * 4 + w) * WPAD + (nt * 32 + l) * 4;
                    float4 v = *(const float4*)&red[wordu];
                    v.x += C[mt][nt][0]; v.y += C[mt][nt][1];
                    v.z += C[mt][nt][2]; v.w += C[mt][nt][3];
                    *(float4*)&red[wordu] = v;
                }
            }
        }
        __syncthreads();

        // ---- final reduce over 4 slots + gates ----
        float gh0[3], gh1[3];
        #pragma unroll
        for (int g = 0; g < 3; g++){
            float4 s = make_float4(0.f, 0.f, 0.f, 0.f);
            #pragma unroll
            for (int sv = 0; sv < 4; sv++){
                float4 v = *(const float4*)&red[(g * 4 + sv) * WPAD + (gntl * 32 + lane_r) * 4];
                s.x += v.x; s.y += v.y; s.z += v.z; s.w += v.w;
            }
            gh0[g] = rp ? s.y : s.x;
            gh1[g] = rp ? s.w : s.z;
        }

        float r0 = sigmoidf_(gir0 + gh0[0] + bhr0);
        float z0 = sigmoidf_(giz0 + gh0[1] + bhz0);
        float n0 = tanhf_(gin0 + r0 * (gh0[2] + bhn0));
        float hn0 = (1.0f - z0) * n0 + z0 * hold0;
        hold0 = hn0;

        float r1 = sigmoidf_(gir1 + gh1[0] + bhr1);
        float z1 = sigmoidf_(giz1 + gh1[1] + bhz1);
        float n1 = tanhf_(gin1 + r1 * (gh1[2] + bhn1));
        float hn1 = (1.0f - z1) * n1 + z1 * hold1;
        hold1 = hn1;

        {
            unsigned x0 = f2bf(hn0);
            unsigned x1 = f2bf(hn0 - bf2f(x0));
            unsigned x2 = f2bf(hn1);
            unsigned x3 = f2bf(hn1 - bf2f(x2));
            unsigned p0 = __shfl_xor_sync(0xffffffffu, x0, 8);
            unsigned p1 = __shfl_xor_sync(0xffffffffu, x1, 8);
            unsigned p2 = __shfl_xor_sync(0xffffffffu, x2, 8);
            unsigned p3 = __shfl_xor_sync(0xffffffffu, x3, 8);
            if ((gjj & 1) == 0){
                int lb = gnc * 4 + (gjj >> 1);
                uint4 v;
                v.x = x0 | (p0 << 16);
                v.y = x2 | (p2 << 16);
                v.z = x1 | (p1 << 16);
                v.w = x3 | (p3 << 16);
                hfw4[((size_t)(ntb + gntl) * 64 + cg) * 32 + lb] = v;
            }
        }

        if (t == T_ - 1){
            g_hT0[(size_t)(c0 + gjj    ) * B_ + gn] = hn0;
            g_hT0[(size_t)(c0 + gjj + 8) * B_ + gn] = hn1;
        }

        bar_t += 1u;
        grid_bar(tid, blk, bar_t);
    }
}

// ---------------- logits = h_final @ W_dense^T + b_dense ----------------
__global__ __launch_bounds__(256) void dense_kernel(const float* __restrict__ Wd,
                                                    const float* __restrict__ bd,
                                                    float* __restrict__ out)
{
    __shared__ __align__(16) float  As[16][72];
    __shared__ __align__(16) float2 Bsd[16][66];

    const int tid = threadIdx.x;
    const int tx = tid & 15;
    const int ty = tid >> 4;
    const int lrow = tid >> 2;
    const int lkq = tid & 3;
    const int kk_ld = tid >> 4;
    const int bq_ld = (tid & 15) * 4;
    const int j0 = blockIdx.x * 64;

    const int jrow = j0 + lrow;
    const bool jok = (jrow < OUT_);
    const float* brow = Wd + (size_t)(jok ? jrow : 0) * H_;

    u64 acc[4][2];
    #pragma unroll
    for (int j = 0; j < 4; j++){ acc[j][0] = 0ull; acc[j][1] = 0ull; }

    for (int k0 = 0; k0 < H_; k0 += 16){
        float4 av = *(const float4*)(g_hT0 + (size_t)(k0 + kk_ld) * B_ + bq_ld);
        float4 bv = make_float4(0.f, 0.f, 0.f, 0.f);
        if (jok) bv = *(const float4*)(brow + k0 + lkq * 4);
        *(float4*)&As[kk_ld][bq_ld] = av;
        Bsd[lkq*4+0][lrow] = make_float2(bv.x, bv.x);
        Bsd[lkq*4+1][lrow] = make_float2(bv.y, bv.y);
        Bsd[lkq*4+2][lrow] = make_float2(bv.z, bv.z);
        Bsd[lkq*4+3][lrow] = make_float2(bv.w, bv.w);
        __syncthreads();
        #pragma unroll
        for (int kk = 0; kk < 16; kk++){
            ulonglong2 a   = *(const ulonglong2*)&As[kk][ty * 4];
            ulonglong2 b01 = *(const ulonglong2*)&Bsd[kk][tx * 4];
            ulonglong2 b23 = *(const ulonglong2*)&Bsd[kk][tx * 4 + 2];
            FMA2(acc[0][0], a.x, b01.x); FMA2(acc[0][1], a.y, b01.x);
            FMA2(acc[1][0], a.x, b01.y); FMA2(acc[1][1], a.y, b01.y);
            FMA2(acc[2][0], a.x, b23.x); FMA2(acc[2][1], a.y, b23.x);
            FMA2(acc[3][0], a.x, b23.y); FMA2(acc[3][1], a.y, b23.y);
        }
        __syncthreads();
    }

    #pragma unroll
    for (int p = 0; p < 2; p++){
        #pragma unroll
        for (int half = 0; half < 2; half++){
            int m = ty * 4 + 2 * p + half;
            #pragma unroll
            for (int jj = 0; jj < 4; jj++){
                int col = j0 + tx * 4 + jj;
                if (col < OUT_){
                    float v = half ? hi32(acc[jj][p]) : lo32(acc[jj][p]);
                    out[(size_t)m * OUT_ + col] = v + bd[col];
                }
            }
        }
    }
}

// ---------------- in-place row-wise log_softmax ----------------
__global__ __launch_bounds__(256) void lsm_kernel(float* __restrict__ out)
{
    __shared__ float red[256];
    const int tid = threadIdx.x;
    float* row = out + (size_t)blockIdx.x * OUT_;

    float m = -1e30f;
    for (int i = tid; i < OUT_; i += 256) m = fmaxf(m, row[i]);
    red[tid] = m; __syncthreads();
    for (int s = 128; s > 0; s >>= 1){
        if (tid < s) red[tid] = fmaxf(red[tid], red[tid + s]);
        __syncthreads();
    }
    float M = red[0];
    __syncthreads();

    float sm = 0.0f;
    for (int i = tid; i < OUT_; i += 256) sm += expf(row[i] - M);
    red[tid] = sm; __syncthreads();
    for (int s = 128; s > 0; s >>= 1){
        if (tid < s) red[tid] += red[tid + s];
        __syncthreads();
    }
    float L = M + logf(red[0]);
    for (int i = tid; i < OUT_; i += 256) row[i] -= L;
}

// ---------------- launch ----------------
extern "C" void kernel_launch(void* const* d_in, const int* in_sizes, int n_in,
                              void* d_out, int out_size)
{
    const float* x    = (const float*)d_in[0];
    const float* Wih  = (const float*)d_in[1];
    const float* Whh  = (const float*)d_in[2];
    const float* bih  = (const float*)d_in[3];
    const float* bhh  = (const float*)d_in[4];
    const float* Wd   = (const float*)d_in[5];
    const float* bd   = (const float*)d_in[6];
    float* out = (float*)d_out;

    const size_t smem_bytes = (size_t)3 * 4 * WPAD * sizeof(float);  // 24768
    cudaFuncSetAttribute(gru_mma, cudaFuncAttributeMaxDynamicSharedMemorySize,
                         (int)smem_bytes);

    init_kernel<<<64, 1024>>>();
    bhh_copy_kernel<<<(H3_ + 255) / 256, 256>>>(bhh);
    wfrag_kernel<<<1536, 256>>>(Whh);
    wihfrag_kernel<<<384, 256>>>(Wih);
    xfrag_kernel<<<8192, 256>>>(x);
    gi_mma<<<dim3(512, 48), 256>>>(bih);
    gru_mma<<<NB, 256, smem_bytes>>>();
    dense_kernel<<<(OUT_ + 63) / 64, 256>>>(Wd, bd, out);
    lsm_kernel<<<B_, 256>>>(out);
}

// round 15
// speedup vs baseline: 4.9133x; 1.1427x over previous
#include <cuda_runtime.h>
#include <math.h>
#include <cstdint>

#define T_    512
#define B_    64
#define IN_   256
#define H_    1024
#define H3_   3072
#define OUT_  50257

#define NB    128         // persistent blocks; block = 16 cols x 32 batches
#define WPAD  516         // padded word stride per (gate,slot) slice
#define MTG_D 3142        // ceil(50257/16) col tiles for dense
#define DBLK  393         // ceil(3142/8) dense blocks

// ---------------- device scratch ----------------
__device__ float g_gi[(size_t)T_ * B_ * H3_];    // [T][B][3H]
__device__ uint4 g_wfrag[64 * 3 * 64 * 32 * 2];  // W_hh frags
__device__ uint4 g_hfrag[2][8 * 64 * 32];        // h frags, double-buffered
__device__ uint4 g_wihfrag[192 * 16 * 64];       // W_ih frags
__device__ uint4 g_xfrag[(size_t)4096 * 16 * 32];// x frags
__device__ uint4 g_wdfrag[(size_t)MTG_D * 64 * 64]; // W_dense frags
__device__ float g_bhh[H3_];
__device__ unsigned g_sub2[2][8 * 32];
__device__ unsigned g_master2[2 * 32];
__device__ unsigned g_phase2[2 * 32];

typedef unsigned long long u64;

#define FMA2(acc, a, b) asm("fma.rn.f32x2 %0, %1, %2, %0;" : "+l"(acc) : "l"(a), "l"(b))

static __device__ __forceinline__ float sigmoidf_(float x){ return 1.0f / (1.0f + expf(-x)); }
static __device__ __forceinline__ float tanhf_(float x){
    float e = expf(-2.0f * fabsf(x));
    float t = (1.0f - e) / (1.0f + e);
    return copysignf(t, x);
}

static __device__ __forceinline__ unsigned f2bf(float f){
    unsigned u = __float_as_uint(f);
    unsigned r = u + 0x7FFFu + ((u >> 16) & 1u);
    return (r >> 16) & 0xFFFFu;
}
static __device__ __forceinline__ float bf2f(unsigned s){
    return __uint_as_float(s << 16);
}
static __device__ __forceinline__ unsigned pack_bf2(float a, float b){
    return f2bf(a) | (f2bf(b) << 16);
}

#define MMA_BF16(C, A, b0v, b1v) \
    asm volatile("mma.sync.aligned.m16n8k16.row.col.f32.bf16.bf16.f32 " \
        "{%0,%1,%2,%3}, {%4,%5,%6,%7}, {%8,%9}, {%0,%1,%2,%3};" \
        : "+f"((C)[0]), "+f"((C)[1]), "+f"((C)[2]), "+f"((C)[3]) \
        : "r"((A).x), "r"((A).y), "r"((A).z), "r"((A).w), "r"(b0v), "r"(b1v))

// ---------------- init ----------------
__global__ void init_kernel(){
    int i = blockIdx.x * blockDim.x + threadIdx.x;
    if (i < 8 * 64 * 32){
        g_hfrag[0][i] = make_uint4(0u, 0u, 0u, 0u);
        g_hfrag[1][i] = make_uint4(0u, 0u, 0u, 0u);
    }
    if (i < 8 * 32){ g_sub2[0][i] = 0u; g_sub2[1][i] = 0u; }
    if (i < 2 * 32){ g_master2[i] = 0u; g_phase2[i] = 0u; }
}

__global__ void bhh_copy_kernel(const float* __restrict__ bhh){
    int i = blockIdx.x * 256 + threadIdx.x;
    if (i < H3_) g_bhh[i] = bhh[i];
}

// ---------------- W_hh -> fragment layout ----------------
__global__ void wfrag_kernel(const float* __restrict__ Whh){
    int gid = blockIdx.x * 256 + threadIdx.x;
    int lane = gid & 31;
    int tile = gid >> 5;
    if (tile >= 64 * 3 * 64) return;
    int ktg = tile & 63;
    int mt  = (tile >> 6) % 3;
    int cg  = tile / 192;
    int c0  = cg * 16;
    int row0 = mt * H_ + c0;
    int j = lane >> 2;
    int k = ktg * 16 + (lane & 3) * 2;

    const float* W = Whh;
    float w00 = W[(size_t)(row0 + j    ) * H_ + k    ];
    float w01 = W[(size_t)(row0 + j    ) * H_ + k + 1];
    float w10 = W[(size_t)(row0 + j + 8) * H_ + k    ];
    float w11 = W[(size_t)(row0 + j + 8) * H_ + k + 1];
    float w02 = W[(size_t)(row0 + j    ) * H_ + k + 8];
    float w03 = W[(size_t)(row0 + j    ) * H_ + k + 9];
    float w12 = W[(size_t)(row0 + j + 8) * H_ + k + 8];
    float w13 = W[(size_t)(row0 + j + 8) * H_ + k + 9];

    uint4 hi, lo;
    hi.x = pack_bf2(w00, w01); hi.y = pack_bf2(w10, w11);
    hi.z = pack_bf2(w02, w03); hi.w = pack_bf2(w12, w13);
    lo.x = pack_bf2(w00 - bf2f(f2bf(w00)), w01 - bf2f(f2bf(w01)));
    lo.y = pack_bf2(w10 - bf2f(f2bf(w10)), w11 - bf2f(f2bf(w11)));
    lo.z = pack_bf2(w02 - bf2f(f2bf(w02)), w03 - bf2f(f2bf(w03)));
    lo.w = pack_bf2(w12 - bf2f(f2bf(w12)), w13 - bf2f(f2bf(w13)));

    g_wfrag[(size_t)tile * 64 + lane * 2    ] = hi;
    g_wfrag[(size_t)tile * 64 + lane * 2 + 1] = lo;
}

// ---------------- W_ih -> fragment layout ----------------
__global__ void wihfrag_kernel(const float* __restrict__ Wih){
    int gid = blockIdx.x * 256 + threadIdx.x;
    int lane = gid & 31;
    int tile = gid >> 5;
    if (tile >= 192 * 16) return;
    int ktg = tile & 15;
    int mtg = tile >> 4;
    int row0 = mtg * 16;
    int j = lane >> 2;
    int k = ktg * 16 + (lane & 3) * 2;

    const float* W = Wih;
    float w00 = W[(size_t)(row0 + j    ) * IN_ + k    ];
    float w01 = W[(size_t)(row0 + j    ) * IN_ + k + 1];
    float w10 = W[(size_t)(row0 + j + 8) * IN_ + k    ];
    float w11 = W[(size_t)(row0 + j + 8) * IN_ + k + 1];
    float w02 = W[(size_t)(row0 + j    ) * IN_ + k + 8];
    float w03 = W[(size_t)(row0 + j    ) * IN_ + k + 9];
    float w12 = W[(size_t)(row0 + j + 8) * IN_ + k + 8];
    float w13 = W[(size_t)(row0 + j + 8) * IN_ + k + 9];

    uint4 hi, lo;
    hi.x = pack_bf2(w00, w01); hi.y = pack_bf2(w10, w11);
    hi.z = pack_bf2(w02, w03); hi.w = pack_bf2(w12, w13);
    lo.x = pack_bf2(w00 - bf2f(f2bf(w00)), w01 - bf2f(f2bf(w01)));
    lo.y = pack_bf2(w10 - bf2f(f2bf(w10)), w11 - bf2f(f2bf(w11)));
    lo.z = pack_bf2(w02 - bf2f(f2bf(w02)), w03 - bf2f(f2bf(w03)));
    lo.w = pack_bf2(w12 - bf2f(f2bf(w12)), w13 - bf2f(f2bf(w13)));

    g_wihfrag[(size_t)tile * 64 + lane * 2    ] = hi;
    g_wihfrag[(size_t)tile * 64 + lane * 2 + 1] = lo;
}

// ---------------- W_dense -> fragment layout (row-guarded) ----------------
__global__ void wdfrag_kernel(const float* __restrict__ Wd){
    int gid = blockIdx.x * 256 + threadIdx.x;
    int lane = gid & 31;
    int tile = gid >> 5;
    if (tile >= MTG_D * 64) return;
    int ktg = tile & 63;
    int mtg = tile >> 6;
    int row0 = mtg * 16;
    int j = lane >> 2;
    int k = ktg * 16 + (lane & 3) * 2;
    int r0 = row0 + j;
    int r1 = row0 + j + 8;
    bool ok0 = (r0 < OUT_);
    bool ok1 = (r1 < OUT_);

    const float* W0 = Wd + (size_t)(ok0 ? r0 : 0) * H_;
    const float* W1 = Wd + (size_t)(ok1 ? r1 : 0) * H_;
    float w00 = ok0 ? W0[k    ] : 0.f;
    float w01 = ok0 ? W0[k + 1] : 0.f;
    float w02 = ok0 ? W0[k + 8] : 0.f;
    float w03 = ok0 ? W0[k + 9] : 0.f;
    float w10 = ok1 ? W1[k    ] : 0.f;
    float w11 = ok1 ? W1[k + 1] : 0.f;
    float w12 = ok1 ? W1[k + 8] : 0.f;
    float w13 = ok1 ? W1[k + 9] : 0.f;

    uint4 hi, lo;
    hi.x = pack_bf2(w00, w01); hi.y = pack_bf2(w10, w11);
    hi.z = pack_bf2(w02, w03); hi.w = pack_bf2(w12, w13);
    lo.x = pack_bf2(w00 - bf2f(f2bf(w00)), w01 - bf2f(f2bf(w01)));
    lo.y = pack_bf2(w10 - bf2f(f2bf(w10)), w11 - bf2f(f2bf(w11)));
    lo.z = pack_bf2(w02 - bf2f(f2bf(w02)), w03 - bf2f(f2bf(w03)));
    lo.w = pack_bf2(w12 - bf2f(f2bf(w12)), w13 - bf2f(f2bf(w13)));

    g_wdfrag[(size_t)tile * 64 + lane * 2    ] = hi;
    g_wdfrag[(size_t)tile * 64 + lane * 2 + 1] = lo;
}

// ---------------- x -> B-fragment layout ----------------
__global__ void xfrag_kernel(const float* __restrict__ x){
    int gid = blockIdx.x * 256 + threadIdx.x;
    int lane = gid & 31;
    int t16 = gid >> 5;
    if (t16 >= 4096 * 16) return;
    int ktg = t16 & 15;
    int nt  = t16 >> 4;
    int n = nt * 8 + (lane >> 2);
    int k = ktg * 16 + (lane & 3) * 2;
    int b = n & 63;
    int t = n >> 6;
    const float* xr = x + ((size_t)b * T_ + t) * IN_;
    float f0 = xr[k], f1 = xr[k + 1], f2 = xr[k + 8], f3 = xr[k + 9];
    uint4 v;
    v.x = pack_bf2(f0, f1);
    v.y = pack_bf2(f2, f3);
    v.z = pack_bf2(f0 - bf2f(f2bf(f0)), f1 - bf2f(f2bf(f1)));
    v.w = pack_bf2(f2 - bf2f(f2bf(f2)), f3 - bf2f(f2bf(f3)));
    g_xfrag[(size_t)t16 * 32 + lane] = v;
}

// ---------------- GI via HMMA ----------------
__global__ __launch_bounds__(256) void gi_mma(const float* __restrict__ bih){
    const int tid = threadIdx.x;
    const int w = tid >> 5;
    const int l = tid & 31;
    const int mtg = blockIdx.y * 4 + (w >> 1);
    const int ntb = blockIdx.x * 8 + (w & 1) * 4;

    float C[4][4];
    #pragma unroll
    for (int q = 0; q < 4; q++)
        #pragma unroll
        for (int r = 0; r < 4; r++) C[q][r] = 0.0f;

    #pragma unroll 4
    for (int ktg = 0; ktg < 16; ktg++){
        size_t ai = ((size_t)mtg * 16 + ktg) * 64 + l * 2;
        uint4 Ah = g_wihfrag[ai];
        uint4 Al = g_wihfrag[ai + 1];
        uint4 Bv[4];
        #pragma unroll
        for (int q = 0; q < 4; q++)
            Bv[q] = g_xfrag[((size_t)(ntb + q) * 16 + ktg) * 32 + l];
        #pragma unroll
        for (int q = 0; q < 4; q++){
            MMA_BF16(C[q], Ah, Bv[q].x, Bv[q].y);
            MMA_BF16(C[q], Ah, Bv[q].z, Bv[q].w);
            MMA_BF16(C[q], Al, Bv[q].x, Bv[q].y);
        }
    }

    const int col0 = mtg * 16 + (l >> 2);
    const int col1 = col0 + 8;
    const float b0 = bih[col0];
    const float b1 = bih[col1];
    #pragma unroll
    for (int q = 0; q < 4; q++){
        int n = (ntb + q) * 8 + (l & 3) * 2;
        g_gi[(size_t)n       * H3_ + col0] = C[q][0] + b0;
        g_gi[(size_t)(n + 1) * H3_ + col0] = C[q][1] + b0;
        g_gi[(size_t)n       * H3_ + col1] = C[q][2] + b1;
        g_gi[(size_t)(n + 1) * H3_ + col1] = C[q][3] + b1;
    }
}

// ---------------- per-half two-level grid barrier ----------------
static __device__ __forceinline__ void grid_bar(int tid, int blk, unsigned target){
    __syncthreads();
    if (tid == 0){
        const int half = blk & 1;
        const int grp  = (blk >> 1) >> 3;
        unsigned a;
        asm volatile("atom.acq_rel.gpu.global.add.u32 %0, [%1], %2;"
                     : "=r"(a) : "l"(&g_sub2[half][grp * 32]), "r"(1u) : "memory");
        bool released = false;
        if (a + 1u == 8u * target){
            unsigned m;
            asm volatile("atom.acq_rel.gpu.global.add.u32 %0, [%1], %2;"
                         : "=r"(m) : "l"(&g_master2[half * 32]), "r"(1u) : "memory");
            if (m + 1u == 8u * target){
                asm volatile("st.release.gpu.global.u32 [%0], %1;"
                             :: "l"(&g_phase2[half * 32]), "r"(target) : "memory");
                released = true;
            }
        }
        if (!released){
            unsigned pcur;
            do {
                asm volatile("ld.acquire.gpu.global.u32 %0, [%1];"
                             : "=r"(pcur) : "l"(&g_phase2[half * 32]) : "memory");
            } while (pcur < target);
        }
    }
    __syncthreads();
}

// ---------------- persistent HMMA recurrence ----------------
__global__ __launch_bounds__(256, 1) void gru_mma()
{
    extern __shared__ float red[];   // [3 gates][4 slots][WPAD]

    const int tid = threadIdx.x;
    const int w   = tid >> 5;
    const int l   = tid & 31;
    const int blk = blockIdx.x;
    const int cg  = blk >> 1;
    const int c0  = cg * 16;
    const int nb0 = (blk & 1) * 32;
    const int ntb = (blk & 1) * 4;

    const int gntl = tid >> 6;
    const int grem = tid & 63;
    const int gjj  = grem >> 3;
    const int gnc  = grem & 7;
    const int gn   = nb0 + gntl * 8 + gnc;
    const int lane_r = gjj * 4 + (gnc >> 1);
    const int rp   = gnc & 1;

    const float bhr0 = g_bhh[c0 + gjj];
    const float bhr1 = g_bhh[c0 + gjj + 8];
    const float bhz0 = g_bhh[H_ + c0 + gjj];
    const float bhz1 = g_bhh[H_ + c0 + gjj + 8];
    const float bhn0 = g_bhh[2 * H_ + c0 + gjj];
    const float bhn1 = g_bhh[2 * H_ + c0 + gjj + 8];

    float hold0 = 0.0f;
    float hold1 = 0.0f;

    const uint4* wf = g_wfrag;
    unsigned bar_t = 0;

    #pragma unroll 1
    for (int t = 0; t < T_; t++){
        const uint4* hfr = g_hfrag[t & 1];
        uint4* hfw4 = &g_hfrag[(t + 1) & 1][0];

        // gi prefetch: L2-only (no reuse; keep W frags resident in L1)
        const float* gA = g_gi + ((size_t)t * B_ + gn) * H3_ + c0 + gjj;
        float gir0 = __ldcg(gA),          gir1 = __ldcg(gA + 8);
        float giz0 = __ldcg(gA + H_),     giz1 = __ldcg(gA + H_ + 8);
        float gin0 = __ldcg(gA + 2 * H_), gin1 = __ldcg(gA + 2 * H_ + 8);

        float C[3][4][4];
        #pragma unroll
        for (int mt = 0; mt < 3; mt++)
            #pragma unroll
            for (int nt = 0; nt < 4; nt++)
                #pragma unroll
                for (int r = 0; r < 4; r++) C[mt][nt][r] = 0.0f;

        // ---- MMA phase: B double-buffered one kt ahead ----
        uint4 Bv[2][4];
        {
            const int ktg0 = w * 8;
            #pragma unroll
            for (int nt = 0; nt < 4; nt++)
                Bv[0][nt] = __ldcg(&hfr[(size_t)((ntb + nt) * 64 + ktg0) * 32 + l]);
        }
        #pragma unroll
        for (int kt = 0; kt < 8; kt++){
            const int ktg = w * 8 + kt;
            const int cur = kt & 1;
            if (kt < 7){
                #pragma unroll
                for (int nt = 0; nt < 4; nt++)
                    Bv[cur ^ 1][nt] = __ldcg(&hfr[(size_t)((ntb + nt) * 64 + ktg + 1) * 32 + l]);
            }
            uint4 Ah[3], Al[3];
            #pragma unroll
            for (int mt = 0; mt < 3; mt++){
                size_t ti = ((size_t)(cg * 3 + mt) * 64 + ktg) * 64 + l * 2;
                Ah[mt] = wf[ti];
                Al[mt] = wf[ti + 1];
            }
            #pragma unroll
            for (int mt = 0; mt < 3; mt++){
                #pragma unroll
                for (int nt = 0; nt < 4; nt++){
                    MMA_BF16(C[mt][nt], Ah[mt], Bv[cur][nt].x, Bv[cur][nt].y);
                    MMA_BF16(C[mt][nt], Ah[mt], Bv[cur][nt].z, Bv[cur][nt].w);
                    MMA_BF16(C[mt][nt], Al[mt], Bv[cur][nt].x, Bv[cur][nt].y);
                }
            }
        }

        // ---- two-phase reduction ----
        if (w >= 4){
            #pragma unroll
            for (int mt = 0; mt < 3; mt++){
                #pragma unroll
                for (int nt = 0; nt < 4; nt++){
                    int wordu = (mt * 4 + (w - 4)) * WPAD + (nt * 32 + l) * 4;
                    *(float4*)&red[wordu] = make_float4(C[mt][nt][0], C[mt][nt][1],
                                                        C[mt][nt][2], C[mt][nt][3]);
                }
            }
        }
        __syncthreads();
        if (w < 4){
            #pragma unroll
            for (int mt = 0; mt < 3; mt++){
                #pragma unroll
                for (int nt = 0; nt < 4; nt++){
                    int wordu = (mt * 4 + w) * WPAD + (nt * 32 + l) * 4;
                    float4 v = *(const float4*)&red[wordu];
                    v.x += C[mt][nt][0]; v.y += C[mt][nt][1];
                    v.z += C[mt][nt][2]; v.w += C[mt][nt][3];
                    *(float4*)&red[wordu] = v;
                }
            }
        }
        __syncthreads();

        // ---- final reduce over 4 slots + gates ----
        float gh0[3], gh1[3];
        #pragma unroll
        for (int g = 0; g < 3; g++){
            float4 s = make_float4(0.f, 0.f, 0.f, 0.f);
            #pragma unroll
            for (int sv = 0; sv < 4; sv++){
                float4 v = *(const float4*)&red[(g * 4 + sv) * WPAD + (gntl * 32 + lane_r) * 4];
                s.x += v.x; s.y += v.y; s.z += v.z; s.w += v.w;
            }
            gh0[g] = rp ? s.y : s.x;
            gh1[g] = rp ? s.w : s.z;
        }

        float r0 = sigmoidf_(gir0 + gh0[0] + bhr0);
        float z0 = sigmoidf_(giz0 + gh0[1] + bhz0);
        float n0 = tanhf_(gin0 + r0 * (gh0[2] + bhn0));
        float hn0 = (1.0f - z0) * n0 + z0 * hold0;
        hold0 = hn0;

        float r1 = sigmoidf_(gir1 + gh1[0] + bhr1);
        float z1 = sigmoidf_(giz1 + gh1[1] + bhz1);
        float n1 = tanhf_(gin1 + r1 * (gh1[2] + bhn1));
        float hn1 = (1.0f - z1) * n1 + z1 * hold1;
        hold1 = hn1;

        {
            unsigned x0 = f2bf(hn0);
            unsigned x1 = f2bf(hn0 - bf2f(x0));
            unsigned x2 = f2bf(hn1);
            unsigned x3 = f2bf(hn1 - bf2f(x2));
            unsigned p0 = __shfl_xor_sync(0xffffffffu, x0, 8);
            unsigned p1 = __shfl_xor_sync(0xffffffffu, x1, 8);
            unsigned p2 = __shfl_xor_sync(0xffffffffu, x2, 8);
            unsigned p3 = __shfl_xor_sync(0xffffffffu, x3, 8);
            if ((gjj & 1) == 0){
                int lb = gnc * 4 + (gjj >> 1);
                uint4 v;
                v.x = x0 | (p0 << 16);
                v.y = x2 | (p2 << 16);
                v.z = x1 | (p1 << 16);
                v.w = x3 | (p3 << 16);
                hfw4[((size_t)(ntb + gntl) * 64 + cg) * 32 + lb] = v;
            }
        }

        bar_t += 1u;
        grid_bar(tid, blk, bar_t);
    }
}

// ---------------- logits via HMMA: out = h @ Wd^T + bd ----------------
// B operand = g_hfrag[0] (final h fragments, produced by gru step t=511).
__global__ __launch_bounds__(256) void dense_mma(const float* __restrict__ bd,
                                                 float* __restrict__ out)
{
    const int tid = threadIdx.x;
    const int w = tid >> 5;
    const int l = tid & 31;
    const int mtg = blockIdx.x * 8 + w;
    if (mtg >= MTG_D) return;

    float C[8][4];
    #pragma unroll
    for (int q = 0; q < 8; q++)
        #pragma unroll
        for (int r = 0; r < 4; r++) C[q][r] = 0.0f;

    #pragma unroll 2
    for (int ktg = 0; ktg < 64; ktg++){
        size_t ai = ((size_t)mtg * 64 + ktg) * 64 + l * 2;
        uint4 Ah = g_wdfrag[ai];
        uint4 Al = g_wdfrag[ai + 1];
        #pragma unroll
        for (int q = 0; q < 8; q++){
            uint4 Bv = g_hfrag[0][(size_t)(q * 64 + ktg) * 32 + l];
            MMA_BF16(C[q], Ah, Bv.x, Bv.y);
            MMA_BF16(C[q], Ah, Bv.z, Bv.w);
            MMA_BF16(C[q], Al, Bv.x, Bv.y);
        }
    }

    const int col0 = mtg * 16 + (l >> 2);
    const int col1 = col0 + 8;
    const bool ok0 = (col0 < OUT_);
    const bool ok1 = (col1 < OUT_);
    const float b0 = ok0 ? bd[col0] : 0.f;
    const float b1 = ok1 ? bd[col1] : 0.f;
    #pragma unroll
    for (int q = 0; q < 8; q++){
        int n = q * 8 + (l & 3) * 2;
        if (ok0){
            out[(size_t)n       * OUT_ + col0] = C[q][0] + b0;
            out[(size_t)(n + 1) * OUT_ + col0] = C[q][1] + b0;
        }
        if (ok1){
            out[(size_t)n       * OUT_ + col1] = C[q][2] + b1;
            out[(size_t)(n + 1) * OUT_ + col1] = C[q][3] + b1;
        }
    }
}

// ---------------- in-place row-wise log_softmax ----------------
__global__ __launch_bounds__(256) void lsm_kernel(float* __restrict__ out)
{
    __shared__ float red[256];
    const int tid = threadIdx.x;
    float* row = out + (size_t)blockIdx.x * OUT_;

    float m = -1e30f;
    for (int i = tid; i < OUT_; i += 256) m = fmaxf(m, row[i]);
    red[tid] = m; __syncthreads();
    for (int s = 128; s > 0; s >>= 1){
        if (tid < s) red[tid] = fmaxf(red[tid], red[tid + s]);
        __syncthreads();
    }
    float M = red[0];
    __syncthreads();

    float sm = 0.0f;
    for (int i = tid; i < OUT_; i += 256) sm += expf(row[i] - M);
    red[tid] = sm; __syncthreads();
    for (int s = 128; s > 0; s >>= 1){
        if (tid < s) red[tid] += red[tid + s];
        __syncthreads();
    }
    float L = M + logf(red[0]);
    for (int i = tid; i < OUT_; i += 256) row[i] -= L;
}

// ---------------- launch ----------------
extern "C" void kernel_launch(void* const* d_in, const int* in_sizes, int n_in,
                              void* d_out, int out_size)
{
    const float* x    = (const float*)d_in[0];
    const float* Wih  = (const float*)d_in[1];
    const float* Whh  = (const float*)d_in[2];
    const float* bih  = (const float*)d_in[3];
    const float* bhh  = (const float*)d_in[4];
    const float* Wd   = (const float*)d_in[5];
    const float* bd   = (const float*)d_in[6];
    float* out = (float*)d_out;

    const size_t smem_bytes = (size_t)3 * 4 * WPAD * sizeof(float);  // 24768
    cudaFuncSetAttribute(gru_mma, cudaFuncAttributeMaxDynamicSharedMemorySize,
                         (int)smem_bytes);

    init_kernel<<<64, 1024>>>();
    bhh_copy_kernel<<<(H3_ + 255) / 256, 256>>>(bhh);
    wfrag_kernel<<<1536, 256>>>(Whh);
    wihfrag_kernel<<<384, 256>>>(Wih);
    wdfrag_kernel<<<(MTG_D * 64 * 32 + 255) / 256, 256>>>(Wd);
    xfrag_kernel<<<8192, 256>>>(x);
    gi_mma<<<dim3(512, 48), 256>>>(bih);
    gru_mma<<<NB, 256, smem_bytes>>>();
    dense_mma<<<DBLK, 256>>>(bd, out);
    lsm_kernel<<<B_, 256>>>(out);
}